// round 3
// baseline (speedup 1.0000x reference)
#include <cuda_runtime.h>
#include <math.h>

#define HID 128
#define OUT 128
#define NMAX 50000
#define ESTRIDE 320   // padded edge-input width (303 real + pad)
#define NSTRIDE 320   // packed node-input width (128 ln + 128 aggr + 64 orig)
#define TILE 64

// Scratch (static __device__ globals; no allocations anywhere)
__device__ float g_aggr[(size_t)NMAX * OUT];
__device__ float g_xsum[(size_t)NMAX * 3];
__device__ float g_cnt[NMAX];

__device__ __forceinline__ float lrelu(float v) { return v > 0.f ? v : 0.01f * v; }

// Inner GEMM micro-tile: each lane owns 4 rows x 8 cols.
// A rows are broadcast smem reads; B is a 32x128 smem tile.
__device__ __forceinline__ void gemm_tile(const float* __restrict__ A, int astride,
                                          const float* __restrict__ wt, int cb,
                                          float acc[4][8])
{
#pragma unroll 8
    for (int kk = 0; kk < 32; ++kk) {
        float a[4];
#pragma unroll
        for (int r = 0; r < 4; ++r) a[r] = A[r * astride + kk];
        const float4 b0 = *(const float4*)(wt + kk * 128 + cb);
        const float4 b1 = *(const float4*)(wt + kk * 128 + cb + 4);
        float b[8] = {b0.x, b0.y, b0.z, b0.w, b1.x, b1.y, b1.z, b1.w};
#pragma unroll
        for (int r = 0; r < 4; ++r)
#pragma unroll
            for (int c = 0; c < 8; ++c)
                acc[r][c] = fmaf(a[r], b[c], acc[r][c]);
    }
}

// Load a 32x128 k-tile of W into smem, zero-padding rows >= krows.
__device__ __forceinline__ void load_wt(float* __restrict__ wt, const float* __restrict__ W,
                                        int k0, int krows, int tid)
{
#pragma unroll 4
    for (int idx = tid; idx < 32 * 128; idx += 256) {
        int kk = idx >> 7, c = idx & 127;
        int k = k0 + kk;
        wt[idx] = (k < krows) ? W[(size_t)k * 128 + c] : 0.f;
    }
}

// ---------------------------------------------------------------------------
// Edge kernel: 64 edges per block.
//   e_in = [feats[src](128) | feats[dst](128) | edge_feats(32) | rbf(15) | pad]
//   h1   = LN(lrelu(e_in @ eW1 + eb1))
//   m    = lrelu(h1 @ eW2 + eb2)
//   c    = lrelu(m @ cW1 + cb1) @ cW2
//   atomics: g_aggr[dst] += m ; g_xsum[dst] += x_rel*c ; g_cnt[dst] += 1
// ---------------------------------------------------------------------------
__global__ __launch_bounds__(256, 1)
void edge_kernel(const float* __restrict__ feats, const float* __restrict__ x,
                 const float* __restrict__ edge_feats,
                 const int* __restrict__ src, const int* __restrict__ dst,
                 const float* __restrict__ eW1, const float* __restrict__ eb1,
                 const float* __restrict__ eg1, const float* __restrict__ ebn1,
                 const float* __restrict__ eW2, const float* __restrict__ eb2,
                 const float* __restrict__ cW1, const float* __restrict__ cb1,
                 const float* __restrict__ cW2, int E)
{
    extern __shared__ float sm[];
    float* ein  = sm;                       // 64 x 320
    float* wt   = ein + TILE * ESTRIDE;     // 32 x 128
    float* h1s  = wt + 32 * 128;            // 64 x 128
    float* ms   = h1s + TILE * 128;         // 64 x 128
    float* xr   = ms + TILE * 128;          // 64 x 3
    int*   sdst = (int*)(xr + TILE * 3);    // 64
    int*   ssrc = sdst + TILE;              // 64

    const int tid = threadIdx.x;
    const int e0 = blockIdx.x * TILE;

    if (tid < TILE) {
        int e = e0 + tid;
        int s = 0, d = 0;
        if (e < E) { s = src[e]; d = dst[e]; }
        ssrc[tid] = s; sdst[tid] = d;
    }
    __syncthreads();

    // Gather features (L2-resident table)
    for (int idx = tid; idx < TILE * HID; idx += 256) {
        int r = idx >> 7, c = idx & 127;
        ein[r * ESTRIDE + c]       = feats[(size_t)ssrc[r] * HID + c];
        ein[r * ESTRIDE + 128 + c] = feats[(size_t)sdst[r] * HID + c];
    }
    for (int idx = tid; idx < TILE * 32; idx += 256) {
        int r = idx >> 5, c = idx & 31;
        int e = e0 + r;
        ein[r * ESTRIDE + 256 + c] = (e < E) ? edge_feats[(size_t)e * 32 + c] : 0.f;
    }
    // Geometry + RBF
    if (tid < TILE) {
        int e = e0 + tid;
        float rx = 0.f, ry = 0.f, rz = 0.f;
        if (e < E) {
            int s = ssrc[tid], d = sdst[tid];
            rx = x[3 * s + 0] - x[3 * d + 0];
            ry = x[3 * s + 1] - x[3 * d + 1];
            rz = x[3 * s + 2] - x[3 * d + 2];
            float nrm = sqrtf(rx * rx + ry * ry + rz * rz) + 1.0f;
            float inv = 1.0f / nrm;
            rx *= inv; ry *= inv; rz *= inv;
        }
        xr[tid * 3 + 0] = rx; xr[tid * 3 + 1] = ry; xr[tid * 3 + 2] = rz;
        float d2 = rx * rx + ry * ry + rz * rz;
        float sig = 1.0f;
#pragma unroll
        for (int i = 0; i < 15; ++i) {
            ein[tid * ESTRIDE + 288 + i] = expf(-d2 / sig);
            sig *= 1.5f;
        }
#pragma unroll
        for (int i = 303; i < ESTRIDE; ++i) ein[tid * ESTRIDE + i] = 0.f;
    }

    const int lane = tid & 31, warp = tid >> 5;
    const int rg = lane >> 4;               // rowgroup within warp
    const int r0 = warp * 8 + rg * 4;       // first of 4 rows this lane owns
    const int cb = (lane & 15) * 8;         // first of 8 cols this lane owns

    float acc[4][8];
#pragma unroll
    for (int r = 0; r < 4; ++r)
#pragma unroll
        for (int c = 0; c < 8; ++c) acc[r][c] = 0.f;

    // ---- GEMM1: e_in(320 padded, 303 real) @ eW1 -> 128
    const float* Arow = ein + r0 * ESTRIDE;
    for (int k0 = 0; k0 < ESTRIDE; k0 += 32) {
        load_wt(wt, eW1, k0, 303, tid);
        __syncthreads();
        gemm_tile(Arow + k0, ESTRIDE, wt, cb, acc);
        __syncthreads();
    }

    // ---- bias + lrelu + LayerNorm -> h1s
    {
        float4 t0 = *(const float4*)(eb1 + cb), t1 = *(const float4*)(eb1 + cb + 4);
        float bb[8] = {t0.x, t0.y, t0.z, t0.w, t1.x, t1.y, t1.z, t1.w};
        float4 g0 = *(const float4*)(eg1 + cb), g1v = *(const float4*)(eg1 + cb + 4);
        float gg[8] = {g0.x, g0.y, g0.z, g0.w, g1v.x, g1v.y, g1v.z, g1v.w};
        float4 q0 = *(const float4*)(ebn1 + cb), q1 = *(const float4*)(ebn1 + cb + 4);
        float qq[8] = {q0.x, q0.y, q0.z, q0.w, q1.x, q1.y, q1.z, q1.w};
#pragma unroll
        for (int rr = 0; rr < 4; ++rr) {
            float v[8]; float s = 0.f, q = 0.f;
#pragma unroll
            for (int c = 0; c < 8; ++c) {
                float t = lrelu(acc[rr][c] + bb[c]);
                v[c] = t; s += t; q += t * t;
            }
#pragma unroll
            for (int off = 8; off >= 1; off >>= 1) {
                s += __shfl_xor_sync(0xffffffffu, s, off);
                q += __shfl_xor_sync(0xffffffffu, q, off);
            }
            float mean = s * (1.f / 128.f);
            float var = q * (1.f / 128.f) - mean * mean;
            float inv = rsqrtf(var + 1e-5f);
            float* hp = h1s + (r0 + rr) * 128 + cb;
#pragma unroll
            for (int c = 0; c < 8; ++c)
                hp[c] = (v[c] - mean) * inv * gg[c] + qq[c];
        }
    }

    // ---- GEMM2: h1 @ eW2 -> m
#pragma unroll
    for (int r = 0; r < 4; ++r)
#pragma unroll
        for (int c = 0; c < 8; ++c) acc[r][c] = 0.f;
    for (int k0 = 0; k0 < 128; k0 += 32) {
        load_wt(wt, eW2, k0, 128, tid);
        __syncthreads();
        gemm_tile(h1s + r0 * 128 + k0, 128, wt, cb, acc);
        __syncthreads();
    }
    {
        float4 t0 = *(const float4*)(eb2 + cb), t1 = *(const float4*)(eb2 + cb + 4);
        float bb[8] = {t0.x, t0.y, t0.z, t0.w, t1.x, t1.y, t1.z, t1.w};
#pragma unroll
        for (int rr = 0; rr < 4; ++rr) {
            float* mp = ms + (r0 + rr) * 128 + cb;
#pragma unroll
            for (int c = 0; c < 8; ++c)
                mp[c] = lrelu(acc[rr][c] + bb[c]);
        }
    }

    // ---- GEMM3: t = lrelu(m @ cW1 + cb1); c = t @ cW2
#pragma unroll
    for (int r = 0; r < 4; ++r)
#pragma unroll
        for (int c = 0; c < 8; ++c) acc[r][c] = 0.f;
    for (int k0 = 0; k0 < 128; k0 += 32) {
        load_wt(wt, cW1, k0, 128, tid);
        __syncthreads();
        gemm_tile(ms + r0 * 128 + k0, 128, wt, cb, acc);
        __syncthreads();
    }
    float cv[4];
    {
        float4 t0 = *(const float4*)(cb1 + cb), t1 = *(const float4*)(cb1 + cb + 4);
        float bb[8] = {t0.x, t0.y, t0.z, t0.w, t1.x, t1.y, t1.z, t1.w};
        float4 w0 = *(const float4*)(cW2 + cb), w1 = *(const float4*)(cW2 + cb + 4);
        float ww[8] = {w0.x, w0.y, w0.z, w0.w, w1.x, w1.y, w1.z, w1.w};
#pragma unroll
        for (int rr = 0; rr < 4; ++rr) {
            float p = 0.f;
#pragma unroll
            for (int c = 0; c < 8; ++c)
                p += lrelu(acc[rr][c] + bb[c]) * ww[c];
#pragma unroll
            for (int off = 8; off >= 1; off >>= 1)
                p += __shfl_xor_sync(0xffffffffu, p, off);
            cv[rr] = p;
        }
    }

    // ---- Aggregation atomics
#pragma unroll
    for (int rr = 0; rr < 4; ++rr) {
        int row = r0 + rr;
        int e = e0 + row;
        if (e < E) {
            int dn = sdst[row];
            float* ab = g_aggr + (size_t)dn * 128 + cb;
            const float* mp = ms + row * 128 + cb;
#pragma unroll
            for (int c = 0; c < 8; ++c)
                atomicAdd(ab + c, mp[c]);
            if ((lane & 15) == rr) {
                atomicAdd(&g_xsum[(size_t)dn * 3 + 0], xr[row * 3 + 0] * cv[rr]);
                atomicAdd(&g_xsum[(size_t)dn * 3 + 1], xr[row * 3 + 1] * cv[rr]);
                atomicAdd(&g_xsum[(size_t)dn * 3 + 2], xr[row * 3 + 2] * cv[rr]);
                atomicAdd(&g_cnt[dn], 1.0f);
            }
        }
    }
}

// ---------------------------------------------------------------------------
// Node kernel: 64 nodes per block.
//   n_in = [LN(feats)(128) | aggr(128) | orig(64)]  (zero mha block skipped;
//          W1 rows remapped: k<256 -> k, k>=256 -> k+128)
//   h    = LN(lrelu(n_in @ nW1 + nb1)); out = h @ nW2 + nb2
//   h_new = 0.75*out + 0.25*feats ; x_new = x + xsum/max(cnt,1)
// ---------------------------------------------------------------------------
__global__ __launch_bounds__(256, 1)
void node_kernel(const float* __restrict__ feats, const float* __restrict__ orig,
                 const float* __restrict__ x,
                 const float* __restrict__ nng, const float* __restrict__ nnb,
                 const float* __restrict__ nW1, const float* __restrict__ nb1,
                 const float* __restrict__ ng1, const float* __restrict__ nbn1,
                 const float* __restrict__ nW2, const float* __restrict__ nb2,
                 float* __restrict__ out, int N)
{
    extern __shared__ float sm[];
    float* nin = sm;                     // 64 x 320
    float* wt  = nin + TILE * NSTRIDE;   // 32 x 128
    float* nh  = wt + 32 * 128;          // 64 x 128

    const int tid = threadIdx.x;
    const int n0 = blockIdx.x * TILE;

    for (int idx = tid; idx < TILE * 128; idx += 256) {
        int r = idx >> 7, c = idx & 127;
        int n = n0 + r;
        nin[r * NSTRIDE + c]       = (n < N) ? feats[(size_t)n * 128 + c] : 0.f;
        nin[r * NSTRIDE + 128 + c] = (n < N) ? g_aggr[(size_t)n * 128 + c] : 0.f;
    }
    for (int idx = tid; idx < TILE * 64; idx += 256) {
        int r = idx >> 6, c = idx & 63;
        int n = n0 + r;
        nin[r * NSTRIDE + 256 + c] = (n < N) ? orig[(size_t)n * 64 + c] : 0.f;
    }
    __syncthreads();

    const int lane = tid & 31, warp = tid >> 5;
    const int rg = lane >> 4;
    const int r0 = warp * 8 + rg * 4;
    const int cb = (lane & 15) * 8;

    // LayerNorm(feats) in place on cols 0..127
    {
        float4 g0 = *(const float4*)(nng + cb), g1v = *(const float4*)(nng + cb + 4);
        float gg[8] = {g0.x, g0.y, g0.z, g0.w, g1v.x, g1v.y, g1v.z, g1v.w};
        float4 q0 = *(const float4*)(nnb + cb), q1 = *(const float4*)(nnb + cb + 4);
        float qq[8] = {q0.x, q0.y, q0.z, q0.w, q1.x, q1.y, q1.z, q1.w};
#pragma unroll
        for (int rr = 0; rr < 4; ++rr) {
            float* rp = nin + (r0 + rr) * NSTRIDE + cb;
            float v[8]; float s = 0.f, q = 0.f;
#pragma unroll
            for (int c = 0; c < 8; ++c) { v[c] = rp[c]; s += v[c]; q += v[c] * v[c]; }
#pragma unroll
            for (int off = 8; off >= 1; off >>= 1) {
                s += __shfl_xor_sync(0xffffffffu, s, off);
                q += __shfl_xor_sync(0xffffffffu, q, off);
            }
            float mean = s * (1.f / 128.f);
            float var = q * (1.f / 128.f) - mean * mean;
            float inv = rsqrtf(var + 1e-5f);
#pragma unroll
            for (int c = 0; c < 8; ++c)
                rp[c] = (v[c] - mean) * inv * gg[c] + qq[c];
        }
    }

    float acc[4][8];
#pragma unroll
    for (int r = 0; r < 4; ++r)
#pragma unroll
        for (int c = 0; c < 8; ++c) acc[r][c] = 0.f;

    // GEMM1: 320-dim packed input, W1 rows remapped past the zero block
    for (int k0 = 0; k0 < NSTRIDE; k0 += 32) {
#pragma unroll 4
        for (int idx = tid; idx < 32 * 128; idx += 256) {
            int kk = idx >> 7, c = idx & 127;
            int k = k0 + kk;
            int kr = (k < 256) ? k : k + 128;
            wt[idx] = nW1[(size_t)kr * 128 + c];
        }
        __syncthreads();
        gemm_tile(nin + r0 * NSTRIDE + k0, NSTRIDE, wt, cb, acc);
        __syncthreads();
    }

    // bias + lrelu + LN -> nh
    {
        float4 t0 = *(const float4*)(nb1 + cb), t1 = *(const float4*)(nb1 + cb + 4);
        float bb[8] = {t0.x, t0.y, t0.z, t0.w, t1.x, t1.y, t1.z, t1.w};
        float4 g0 = *(const float4*)(ng1 + cb), g1v = *(const float4*)(ng1 + cb + 4);
        float gg[8] = {g0.x, g0.y, g0.z, g0.w, g1v.x, g1v.y, g1v.z, g1v.w};
        float4 q0 = *(const float4*)(nbn1 + cb), q1 = *(const float4*)(nbn1 + cb + 4);
        float qq[8] = {q0.x, q0.y, q0.z, q0.w, q1.x, q1.y, q1.z, q1.w};
#pragma unroll
        for (int rr = 0; rr < 4; ++rr) {
            float v[8]; float s = 0.f, q = 0.f;
#pragma unroll
            for (int c = 0; c < 8; ++c) {
                float t = lrelu(acc[rr][c] + bb[c]);
                v[c] = t; s += t; q += t * t;
            }
#pragma unroll
            for (int off = 8; off >= 1; off >>= 1) {
                s += __shfl_xor_sync(0xffffffffu, s, off);
                q += __shfl_xor_sync(0xffffffffu, q, off);
            }
            float mean = s * (1.f / 128.f);
            float var = q * (1.f / 128.f) - mean * mean;
            float inv = rsqrtf(var + 1e-5f);
            float* hp = nh + (r0 + rr) * 128 + cb;
#pragma unroll
            for (int c = 0; c < 8; ++c)
                hp[c] = (v[c] - mean) * inv * gg[c] + qq[c];
        }
    }

    // GEMM2: nh @ nW2
#pragma unroll
    for (int r = 0; r < 4; ++r)
#pragma unroll
        for (int c = 0; c < 8; ++c) acc[r][c] = 0.f;
    for (int k0 = 0; k0 < 128; k0 += 32) {
        load_wt(wt, nW2, k0, 128, tid);
        __syncthreads();
        gemm_tile(nh + r0 * 128 + k0, 128, wt, cb, acc);
        __syncthreads();
    }

    // Outputs
    {
        float4 t0 = *(const float4*)(nb2 + cb), t1 = *(const float4*)(nb2 + cb + 4);
        float bb[8] = {t0.x, t0.y, t0.z, t0.w, t1.x, t1.y, t1.z, t1.w};
#pragma unroll
        for (int rr = 0; rr < 4; ++rr) {
            int n = n0 + r0 + rr;
            if (n < N) {
                const float* fp = feats + (size_t)n * 128 + cb;
                float* op = out + (size_t)n * 128 + cb;
#pragma unroll
                for (int c = 0; c < 8; ++c) {
                    float o = acc[rr][c] + bb[c];
                    op[c] = 0.75f * o + 0.25f * fp[c];
                }
            }
        }
    }
    if (tid < TILE) {
        int n = n0 + tid;
        if (n < N) {
            float cnt = g_cnt[n];
            if (cnt < 1.f) cnt = 1.f;
            float inv = 1.f / cnt;
            size_t base = (size_t)N * 128 + (size_t)n * 3;
            out[base + 0] = x[(size_t)n * 3 + 0] + g_xsum[(size_t)n * 3 + 0] * inv;
            out[base + 1] = x[(size_t)n * 3 + 1] + g_xsum[(size_t)n * 3 + 1] * inv;
            out[base + 2] = x[(size_t)n * 3 + 2] + g_xsum[(size_t)n * 3 + 2] * inv;
        }
    }
}

extern "C" void kernel_launch(void* const* d_in, const int* in_sizes, int n_in,
                              void* d_out, int out_size)
{
    const float* feats      = (const float*)d_in[0];
    const float* orig       = (const float*)d_in[1];
    const float* x          = (const float*)d_in[2];
    /* d_in[3] = x_orig, unused (X_CONN_INIT = 0) */
    const float* edge_feats = (const float*)d_in[4];
    const int*   src        = (const int*)d_in[5];
    const int*   dst        = (const int*)d_in[6];
    const float* eW1  = (const float*)d_in[7];
    const float* eb1  = (const float*)d_in[8];
    const float* eg1  = (const float*)d_in[9];
    const float* ebn1 = (const float*)d_in[10];
    const float* eW2  = (const float*)d_in[11];
    const float* eb2  = (const float*)d_in[12];
    const float* nng  = (const float*)d_in[13];
    const float* nnb  = (const float*)d_in[14];
    const float* nW1  = (const float*)d_in[15];
    const float* nb1  = (const float*)d_in[16];
    const float* ng1  = (const float*)d_in[17];
    const float* nbn1 = (const float*)d_in[18];
    const float* nW2  = (const float*)d_in[19];
    const float* nb2  = (const float*)d_in[20];
    const float* cW1  = (const float*)d_in[21];
    const float* cb1  = (const float*)d_in[22];
    const float* cW2  = (const float*)d_in[23];

    const int N = in_sizes[0] / HID;
    const int E = in_sizes[5];

    void *aggr_p, *xs_p, *cnt_p;
    cudaGetSymbolAddress(&aggr_p, g_aggr);
    cudaGetSymbolAddress(&xs_p, g_xsum);
    cudaGetSymbolAddress(&cnt_p, g_cnt);
    cudaMemsetAsync(aggr_p, 0, (size_t)N * OUT * sizeof(float), 0);
    cudaMemsetAsync(xs_p, 0, (size_t)N * 3 * sizeof(float), 0);
    cudaMemsetAsync(cnt_p, 0, (size_t)N * sizeof(float), 0);

    const int SMEM_E = (TILE * ESTRIDE + 32 * 128 + TILE * 128 * 2 + TILE * 3) * 4
                       + TILE * 2 * (int)sizeof(int);
    const int SMEM_N = (TILE * NSTRIDE + 32 * 128 + TILE * 128) * 4;
    cudaFuncSetAttribute(edge_kernel, cudaFuncAttributeMaxDynamicSharedMemorySize, SMEM_E);
    cudaFuncSetAttribute(node_kernel, cudaFuncAttributeMaxDynamicSharedMemorySize, SMEM_N);

    int eblocks = (E + TILE - 1) / TILE;
    edge_kernel<<<eblocks, 256, SMEM_E>>>(feats, x, edge_feats, src, dst,
                                          eW1, eb1, eg1, ebn1, eW2, eb2,
                                          cW1, cb1, cW2, E);

    int nblocks = (N + TILE - 1) / TILE;
    node_kernel<<<nblocks, 256, SMEM_N>>>(feats, orig, x, nng, nnb,
                                          nW1, nb1, ng1, nbn1, nW2, nb2,
                                          (float*)d_out, N);
}

// round 4
// speedup vs baseline: 1.5469x; 1.5469x over previous
#include <cuda_runtime.h>
#include <math.h>

#define HID 128
#define OUT 128
#define NMAX 50000
#define ESTRIDE 324   // padded edge/node-input stride (conflict-free: 4*324 % 32 = 16)
#define HSTRIDE 132   // hidden-buffer stride (4*132 % 32 = 16)
#define TILE 64

// Scratch (static __device__ globals; no allocations anywhere)
__device__ float g_aggr[(size_t)NMAX * OUT];
__device__ float g_xsum[(size_t)NMAX * 3];
__device__ float g_cnt[NMAX];

__device__ __forceinline__ float lrelu(float v) { return v > 0.f ? v : 0.01f * v; }

// Inner GEMM micro-tile: each lane owns 4 rows x 8 cols.
__device__ __forceinline__ void gemm_tile(const float* __restrict__ A, int astride,
                                          const float* __restrict__ wt, int cb,
                                          float acc[4][8])
{
#pragma unroll 8
    for (int kk = 0; kk < 32; ++kk) {
        float a[4];
#pragma unroll
        for (int r = 0; r < 4; ++r) a[r] = A[r * astride + kk];
        const float4 b0 = *(const float4*)(wt + kk * 128 + cb);
        const float4 b1 = *(const float4*)(wt + kk * 128 + cb + 4);
        float b[8] = {b0.x, b0.y, b0.z, b0.w, b1.x, b1.y, b1.z, b1.w};
#pragma unroll
        for (int r = 0; r < 4; ++r)
#pragma unroll
            for (int c = 0; c < 8; ++c)
                acc[r][c] = fmaf(a[r], b[c], acc[r][c]);
    }
}

// Register prefetch of a 32x128 weight k-tile (16 floats / thread).
template<bool REMAP>
__device__ __forceinline__ void ldg_wt(float4 r[4], const float* __restrict__ W,
                                       int k0, int krows, int tid)
{
#pragma unroll
    for (int j = 0; j < 4; ++j) {
        int flat = (tid + j * 256) << 2;
        int kk = flat >> 7, c = flat & 127;
        int k = k0 + kk;
        if (REMAP) {
            int kr = (k < 256) ? k : k + 128;   // skip the 128-wide zero (mha) block
            r[j] = *(const float4*)(W + (size_t)kr * 128 + c);
        } else {
            r[j] = (k < krows) ? *(const float4*)(W + (size_t)k * 128 + c)
                               : make_float4(0.f, 0.f, 0.f, 0.f);
        }
    }
}

__device__ __forceinline__ void sts_wt(float* __restrict__ wt, const float4 r[4], int tid)
{
#pragma unroll
    for (int j = 0; j < 4; ++j)
        *(float4*)(wt + ((tid + j * 256) << 2)) = r[j];
}

// k-tiled GEMM with register-prefetched weight tiles (1 smem tile, LDG overlapped).
template<bool REMAP>
__device__ __forceinline__ void gemm_run(const float* __restrict__ A, int astride,
                                         const float* __restrict__ W, int krows, int ntiles,
                                         float* __restrict__ wt, int tid, int cb,
                                         float acc[4][8])
{
    float4 rw[4];
    ldg_wt<REMAP>(rw, W, 0, krows, tid);
#pragma unroll 1
    for (int t = 0; t < ntiles; ++t) {
        __syncthreads();                       // previous consumers of wt done
        sts_wt(wt, rw, tid);
        if (t + 1 < ntiles) ldg_wt<REMAP>(rw, W, (t + 1) * 32, krows, tid);
        __syncthreads();                       // wt tile ready
        gemm_tile(A + t * 32, astride, wt, cb, acc);
    }
}

// ---------------------------------------------------------------------------
// Edge kernel: 64 edges per block, 2 CTAs/SM.
// ---------------------------------------------------------------------------
__global__ __launch_bounds__(256, 2)
void edge_kernel(const float* __restrict__ feats, const float* __restrict__ x,
                 const float* __restrict__ edge_feats,
                 const int* __restrict__ src, const int* __restrict__ dst,
                 const float* __restrict__ eW1, const float* __restrict__ eb1,
                 const float* __restrict__ eg1, const float* __restrict__ ebn1,
                 const float* __restrict__ eW2, const float* __restrict__ eb2,
                 const float* __restrict__ cW1, const float* __restrict__ cb1,
                 const float* __restrict__ cW2, int E)
{
    extern __shared__ float sm[];
    float* ein  = sm;                        // 64 x 324
    float* wt   = ein + TILE * ESTRIDE;      // 32 x 128
    float* xr   = wt + 32 * 128;             // 64 x 3
    int*   sdst = (int*)(xr + TILE * 3);     // 64
    int*   ssrc = sdst + TILE;               // 64
    float* h1s  = ein;                       // overlay, 64 x 132
    float* ms   = ein + TILE * HSTRIDE;      // overlay, 64 x 132

    const int tid = threadIdx.x;
    const int e0 = blockIdx.x * TILE;

    if (tid < TILE) {
        int e = e0 + tid;
        int s = 0, d = 0;
        if (e < E) { s = src[e]; d = dst[e]; }
        ssrc[tid] = s; sdst[tid] = d;
    }
    __syncthreads();

    // Gather features (L2-resident table)
    for (int idx = tid; idx < TILE * HID; idx += 256) {
        int r = idx >> 7, c = idx & 127;
        ein[r * ESTRIDE + c]       = feats[(size_t)ssrc[r] * HID + c];
        ein[r * ESTRIDE + 128 + c] = feats[(size_t)sdst[r] * HID + c];
    }
    for (int idx = tid; idx < TILE * 32; idx += 256) {
        int r = idx >> 5, c = idx & 31;
        int e = e0 + r;
        ein[r * ESTRIDE + 256 + c] = (e < E) ? edge_feats[(size_t)e * 32 + c] : 0.f;
    }
    // Geometry + RBF
    if (tid < TILE) {
        int e = e0 + tid;
        float rx = 0.f, ry = 0.f, rz = 0.f;
        if (e < E) {
            int s = ssrc[tid], d = sdst[tid];
            rx = x[3 * s + 0] - x[3 * d + 0];
            ry = x[3 * s + 1] - x[3 * d + 1];
            rz = x[3 * s + 2] - x[3 * d + 2];
            float nrm = sqrtf(rx * rx + ry * ry + rz * rz) + 1.0f;
            float inv = 1.0f / nrm;
            rx *= inv; ry *= inv; rz *= inv;
        }
        xr[tid * 3 + 0] = rx; xr[tid * 3 + 1] = ry; xr[tid * 3 + 2] = rz;
        float d2 = rx * rx + ry * ry + rz * rz;
        float sig = 1.0f;
#pragma unroll
        for (int i = 0; i < 15; ++i) {
            ein[tid * ESTRIDE + 288 + i] = expf(-d2 / sig);
            sig *= 1.5f;
        }
#pragma unroll
        for (int i = 303; i < 320; ++i) ein[tid * ESTRIDE + i] = 0.f;
    }

    const int lane = tid & 31, warp = tid >> 5;
    const int rg = lane >> 4;
    const int r0 = warp * 8 + rg * 4;
    const int cb = (lane & 15) * 8;

    float acc[4][8];
#pragma unroll
    for (int r = 0; r < 4; ++r)
#pragma unroll
        for (int c = 0; c < 8; ++c) acc[r][c] = 0.f;

    // ---- GEMM1: e_in(320, 303 real) @ eW1 -> 128
    gemm_run<false>(ein + r0 * ESTRIDE, ESTRIDE, eW1, 303, 10, wt, tid, cb, acc);
    __syncthreads();   // all warps done reading ein before the h1s overlay write

    // ---- bias + lrelu + LayerNorm -> h1s (overlay)
    {
        float4 t0 = *(const float4*)(eb1 + cb), t1 = *(const float4*)(eb1 + cb + 4);
        float bb[8] = {t0.x, t0.y, t0.z, t0.w, t1.x, t1.y, t1.z, t1.w};
        float4 g0 = *(const float4*)(eg1 + cb), g1v = *(const float4*)(eg1 + cb + 4);
        float gg[8] = {g0.x, g0.y, g0.z, g0.w, g1v.x, g1v.y, g1v.z, g1v.w};
        float4 q0 = *(const float4*)(ebn1 + cb), q1 = *(const float4*)(ebn1 + cb + 4);
        float qq[8] = {q0.x, q0.y, q0.z, q0.w, q1.x, q1.y, q1.z, q1.w};
#pragma unroll
        for (int rr = 0; rr < 4; ++rr) {
            float v[8]; float s = 0.f, q = 0.f;
#pragma unroll
            for (int c = 0; c < 8; ++c) {
                float t = lrelu(acc[rr][c] + bb[c]);
                v[c] = t; s += t; q += t * t;
            }
#pragma unroll
            for (int off = 8; off >= 1; off >>= 1) {
                s += __shfl_xor_sync(0xffffffffu, s, off);
                q += __shfl_xor_sync(0xffffffffu, q, off);
            }
            float mean = s * (1.f / 128.f);
            float var = q * (1.f / 128.f) - mean * mean;
            float inv = rsqrtf(var + 1e-5f);
            float* hp = h1s + (r0 + rr) * HSTRIDE + cb;
#pragma unroll
            for (int c = 0; c < 8; ++c)
                hp[c] = (v[c] - mean) * inv * gg[c] + qq[c];
        }
    }

    // ---- GEMM2: h1 @ eW2 -> m
#pragma unroll
    for (int r = 0; r < 4; ++r)
#pragma unroll
        for (int c = 0; c < 8; ++c) acc[r][c] = 0.f;
    gemm_run<false>(h1s + r0 * HSTRIDE, HSTRIDE, eW2, 128, 4, wt, tid, cb, acc);
    {
        float4 t0 = *(const float4*)(eb2 + cb), t1 = *(const float4*)(eb2 + cb + 4);
        float bb[8] = {t0.x, t0.y, t0.z, t0.w, t1.x, t1.y, t1.z, t1.w};
#pragma unroll
        for (int rr = 0; rr < 4; ++rr) {
            float* mp = ms + (r0 + rr) * HSTRIDE + cb;
#pragma unroll
            for (int c = 0; c < 8; ++c)
                mp[c] = lrelu(acc[rr][c] + bb[c]);
        }
    }

    // ---- GEMM3: t = lrelu(m @ cW1 + cb1); c = t @ cW2
#pragma unroll
    for (int r = 0; r < 4; ++r)
#pragma unroll
        for (int c = 0; c < 8; ++c) acc[r][c] = 0.f;
    gemm_run<false>(ms + r0 * HSTRIDE, HSTRIDE, cW1, 128, 4, wt, tid, cb, acc);

    float cv[4];
    {
        float4 t0 = *(const float4*)(cb1 + cb), t1 = *(const float4*)(cb1 + cb + 4);
        float bb[8] = {t0.x, t0.y, t0.z, t0.w, t1.x, t1.y, t1.z, t1.w};
        float4 w0 = *(const float4*)(cW2 + cb), w1 = *(const float4*)(cW2 + cb + 4);
        float ww[8] = {w0.x, w0.y, w0.z, w0.w, w1.x, w1.y, w1.z, w1.w};
#pragma unroll
        for (int rr = 0; rr < 4; ++rr) {
            float p = 0.f;
#pragma unroll
            for (int c = 0; c < 8; ++c)
                p += lrelu(acc[rr][c] + bb[c]) * ww[c];
#pragma unroll
            for (int off = 8; off >= 1; off >>= 1)
                p += __shfl_xor_sync(0xffffffffu, p, off);
            cv[rr] = p;
        }
    }

    // ---- Aggregation atomics
#pragma unroll
    for (int rr = 0; rr < 4; ++rr) {
        int row = r0 + rr;
        int e = e0 + row;
        if (e < E) {
            int dn = sdst[row];
            float* ab = g_aggr + (size_t)dn * 128 + cb;
            const float* mp = ms + row * HSTRIDE + cb;
#pragma unroll
            for (int c = 0; c < 8; ++c)
                atomicAdd(ab + c, mp[c]);
            if ((lane & 15) == rr) {
                atomicAdd(&g_xsum[(size_t)dn * 3 + 0], xr[row * 3 + 0] * cv[rr]);
                atomicAdd(&g_xsum[(size_t)dn * 3 + 1], xr[row * 3 + 1] * cv[rr]);
                atomicAdd(&g_xsum[(size_t)dn * 3 + 2], xr[row * 3 + 2] * cv[rr]);
                atomicAdd(&g_cnt[dn], 1.0f);
            }
        }
    }
}

// ---------------------------------------------------------------------------
// Node kernel: 64 nodes per block, 2 CTAs/SM.
// ---------------------------------------------------------------------------
__global__ __launch_bounds__(256, 2)
void node_kernel(const float* __restrict__ feats, const float* __restrict__ orig,
                 const float* __restrict__ x,
                 const float* __restrict__ nng, const float* __restrict__ nnb,
                 const float* __restrict__ nW1, const float* __restrict__ nb1,
                 const float* __restrict__ ng1, const float* __restrict__ nbn1,
                 const float* __restrict__ nW2, const float* __restrict__ nb2,
                 float* __restrict__ out, int N)
{
    extern __shared__ float sm[];
    float* nin = sm;                      // 64 x 324 (320 used)
    float* wt  = nin + TILE * ESTRIDE;    // 32 x 128
    float* nh  = nin;                     // overlay, 64 x 132

    const int tid = threadIdx.x;
    const int n0 = blockIdx.x * TILE;

    for (int idx = tid; idx < TILE * 128; idx += 256) {
        int r = idx >> 7, c = idx & 127;
        int n = n0 + r;
        nin[r * ESTRIDE + c]       = (n < N) ? feats[(size_t)n * 128 + c] : 0.f;
        nin[r * ESTRIDE + 128 + c] = (n < N) ? g_aggr[(size_t)n * 128 + c] : 0.f;
    }
    for (int idx = tid; idx < TILE * 64; idx += 256) {
        int r = idx >> 6, c = idx & 63;
        int n = n0 + r;
        nin[r * ESTRIDE + 256 + c] = (n < N) ? orig[(size_t)n * 64 + c] : 0.f;
    }
    __syncthreads();

    const int lane = tid & 31, warp = tid >> 5;
    const int rg = lane >> 4;
    const int r0 = warp * 8 + rg * 4;
    const int cb = (lane & 15) * 8;

    // LayerNorm(feats) in place on cols 0..127
    {
        float4 g0 = *(const float4*)(nng + cb), g1v = *(const float4*)(nng + cb + 4);
        float gg[8] = {g0.x, g0.y, g0.z, g0.w, g1v.x, g1v.y, g1v.z, g1v.w};
        float4 q0 = *(const float4*)(nnb + cb), q1 = *(const float4*)(nnb + cb + 4);
        float qq[8] = {q0.x, q0.y, q0.z, q0.w, q1.x, q1.y, q1.z, q1.w};
#pragma unroll
        for (int rr = 0; rr < 4; ++rr) {
            float* rp = nin + (r0 + rr) * ESTRIDE + cb;
            float v[8]; float s = 0.f, q = 0.f;
#pragma unroll
            for (int c = 0; c < 8; ++c) { v[c] = rp[c]; s += v[c]; q += v[c] * v[c]; }
#pragma unroll
            for (int off = 8; off >= 1; off >>= 1) {
                s += __shfl_xor_sync(0xffffffffu, s, off);
                q += __shfl_xor_sync(0xffffffffu, q, off);
            }
            float mean = s * (1.f / 128.f);
            float var = q * (1.f / 128.f) - mean * mean;
            float inv = rsqrtf(var + 1e-5f);
#pragma unroll
            for (int c = 0; c < 8; ++c)
                rp[c] = (v[c] - mean) * inv * gg[c] + qq[c];
        }
    }
    __syncthreads();

    float acc[4][8];
#pragma unroll
    for (int r = 0; r < 4; ++r)
#pragma unroll
        for (int c = 0; c < 8; ++c) acc[r][c] = 0.f;

    // GEMM1: 320-dim packed input; W1 rows remapped past the zero (mha) block
    gemm_run<true>(nin + r0 * ESTRIDE, ESTRIDE, nW1, 448, 10, wt, tid, cb, acc);
    __syncthreads();   // all warps done reading nin before the nh overlay write

    // bias + lrelu + LN -> nh (overlay)
    {
        float4 t0 = *(const float4*)(nb1 + cb), t1 = *(const float4*)(nb1 + cb + 4);
        float bb[8] = {t0.x, t0.y, t0.z, t0.w, t1.x, t1.y, t1.z, t1.w};
        float4 g0 = *(const float4*)(ng1 + cb), g1v = *(const float4*)(ng1 + cb + 4);
        float gg[8] = {g0.x, g0.y, g0.z, g0.w, g1v.x, g1v.y, g1v.z, g1v.w};
        float4 q0 = *(const float4*)(nbn1 + cb), q1 = *(const float4*)(nbn1 + cb + 4);
        float qq[8] = {q0.x, q0.y, q0.z, q0.w, q1.x, q1.y, q1.z, q1.w};
#pragma unroll
        for (int rr = 0; rr < 4; ++rr) {
            float v[8]; float s = 0.f, q = 0.f;
#pragma unroll
            for (int c = 0; c < 8; ++c) {
                float t = lrelu(acc[rr][c] + bb[c]);
                v[c] = t; s += t; q += t * t;
            }
#pragma unroll
            for (int off = 8; off >= 1; off >>= 1) {
                s += __shfl_xor_sync(0xffffffffu, s, off);
                q += __shfl_xor_sync(0xffffffffu, q, off);
            }
            float mean = s * (1.f / 128.f);
            float var = q * (1.f / 128.f) - mean * mean;
            float inv = rsqrtf(var + 1e-5f);
            float* hp = nh + (r0 + rr) * HSTRIDE + cb;
#pragma unroll
            for (int c = 0; c < 8; ++c)
                hp[c] = (v[c] - mean) * inv * gg[c] + qq[c];
        }
    }

    // GEMM2: nh @ nW2
#pragma unroll
    for (int r = 0; r < 4; ++r)
#pragma unroll
        for (int c = 0; c < 8; ++c) acc[r][c] = 0.f;
    gemm_run<false>(nh + r0 * HSTRIDE, HSTRIDE, nW2, 128, 4, wt, tid, cb, acc);

    // Outputs
    {
        float4 t0 = *(const float4*)(nb2 + cb), t1 = *(const float4*)(nb2 + cb + 4);
        float bb[8] = {t0.x, t0.y, t0.z, t0.w, t1.x, t1.y, t1.z, t1.w};
#pragma unroll
        for (int rr = 0; rr < 4; ++rr) {
            int n = n0 + r0 + rr;
            if (n < N) {
                const float* fp = feats + (size_t)n * 128 + cb;
                float* op = out + (size_t)n * 128 + cb;
#pragma unroll
                for (int c = 0; c < 8; ++c) {
                    float o = acc[rr][c] + bb[c];
                    op[c] = 0.75f * o + 0.25f * fp[c];
                }
            }
        }
    }
    if (tid < TILE) {
        int n = n0 + tid;
        if (n < N) {
            float cnt = g_cnt[n];
            if (cnt < 1.f) cnt = 1.f;
            float inv = 1.f / cnt;
            size_t base = (size_t)N * 128 + (size_t)n * 3;
            out[base + 0] = x[(size_t)n * 3 + 0] + g_xsum[(size_t)n * 3 + 0] * inv;
            out[base + 1] = x[(size_t)n * 3 + 1] + g_xsum[(size_t)n * 3 + 1] * inv;
            out[base + 2] = x[(size_t)n * 3 + 2] + g_xsum[(size_t)n * 3 + 2] * inv;
        }
    }
}

extern "C" void kernel_launch(void* const* d_in, const int* in_sizes, int n_in,
                              void* d_out, int out_size)
{
    const float* feats      = (const float*)d_in[0];
    const float* orig       = (const float*)d_in[1];
    const float* x          = (const float*)d_in[2];
    /* d_in[3] = x_orig, unused (X_CONN_INIT = 0) */
    const float* edge_feats = (const float*)d_in[4];
    const int*   src        = (const int*)d_in[5];
    const int*   dst        = (const int*)d_in[6];
    const float* eW1  = (const float*)d_in[7];
    const float* eb1  = (const float*)d_in[8];
    const float* eg1  = (const float*)d_in[9];
    const float* ebn1 = (const float*)d_in[10];
    const float* eW2  = (const float*)d_in[11];
    const float* eb2  = (const float*)d_in[12];
    const float* nng  = (const float*)d_in[13];
    const float* nnb  = (const float*)d_in[14];
    const float* nW1  = (const float*)d_in[15];
    const float* nb1  = (const float*)d_in[16];
    const float* ng1  = (const float*)d_in[17];
    const float* nbn1 = (const float*)d_in[18];
    const float* nW2  = (const float*)d_in[19];
    const float* nb2  = (const float*)d_in[20];
    const float* cW1  = (const float*)d_in[21];
    const float* cb1  = (const float*)d_in[22];
    const float* cW2  = (const float*)d_in[23];

    const int N = in_sizes[0] / HID;
    const int E = in_sizes[5];

    void *aggr_p, *xs_p, *cnt_p;
    cudaGetSymbolAddress(&aggr_p, g_aggr);
    cudaGetSymbolAddress(&xs_p, g_xsum);
    cudaGetSymbolAddress(&cnt_p, g_cnt);
    cudaMemsetAsync(aggr_p, 0, (size_t)N * OUT * sizeof(float), 0);
    cudaMemsetAsync(xs_p, 0, (size_t)N * 3 * sizeof(float), 0);
    cudaMemsetAsync(cnt_p, 0, (size_t)N * sizeof(float), 0);

    const int SMEM_E = (TILE * ESTRIDE + 32 * 128 + TILE * 3) * 4
                       + TILE * 2 * (int)sizeof(int);              // ~100.6 KB
    const int SMEM_N = (TILE * ESTRIDE + 32 * 128) * 4;            // ~99.3 KB
    cudaFuncSetAttribute(edge_kernel, cudaFuncAttributeMaxDynamicSharedMemorySize, SMEM_E);
    cudaFuncSetAttribute(node_kernel, cudaFuncAttributeMaxDynamicSharedMemorySize, SMEM_N);

    int eblocks = (E + TILE - 1) / TILE;
    edge_kernel<<<eblocks, 256, SMEM_E>>>(feats, x, edge_feats, src, dst,
                                          eW1, eb1, eg1, ebn1, eW2, eb2,
                                          cW1, cb1, cW2, E);

    int nblocks = (N + TILE - 1) / TILE;
    node_kernel<<<nblocks, 256, SMEM_N>>>(feats, orig, x, nng, nnb,
                                          nW1, nb1, ng1, nbn1, nW2, nb2,
                                          (float*)d_out, N);
}

// round 5
// speedup vs baseline: 1.5727x; 1.0166x over previous
#include <cuda_runtime.h>
#include <math.h>

#define HID 128
#define OUT 128
#define NMAX 50000
#define ESTRIDE 324   // padded edge/node-input stride (16B-aligned rows, conflict-free)
#define HSTRIDE 132   // hidden-buffer stride (16B-aligned rows)
#define TILE 64

// Scratch (static __device__ globals; no allocations anywhere)
__device__ float g_aggr[(size_t)NMAX * OUT];
__device__ float g_xsum[(size_t)NMAX * 3];
__device__ float g_cnt[NMAX];

__device__ __forceinline__ float lrelu(float v) { return v > 0.f ? v : 0.01f * v; }

typedef unsigned long long u64;

__device__ __forceinline__ u64 pack2(float v) {
    u64 p;
    asm("mov.b64 %0, {%1, %1};" : "=l"(p) : "f"(v));
    return p;
}
__device__ __forceinline__ float2 unpack2(u64 v) {
    float2 f;
    asm("mov.b64 {%0, %1}, %2;" : "=f"(f.x), "=f"(f.y) : "l"(v));
    return f;
}
__device__ __forceinline__ void ffma2(u64& d, u64 a, u64 b) {
    asm("fma.rn.f32x2 %0, %1, %2, %0;" : "+l"(d) : "l"(a), "l"(b));
}

// Inner GEMM micro-tile: each lane owns 4 rows x 8 cols (4 f32x2 pairs).
// A loaded as float4 along k (broadcast LDS.128), B read as packed f32x2 pairs.
__device__ __forceinline__ void gemm_tile(const float* __restrict__ A, int astride,
                                          const float* __restrict__ wt, int cb,
                                          u64 acc[4][4])
{
#pragma unroll
    for (int kq = 0; kq < 8; ++kq) {
        float4 a4[4];
#pragma unroll
        for (int r = 0; r < 4; ++r)
            a4[r] = *(const float4*)(A + r * astride + kq * 4);
#pragma unroll
        for (int k = 0; k < 4; ++k) {
            const float* wrow = wt + (kq * 4 + k) * 128 + cb;
            const ulonglong2 b0 = *(const ulonglong2*)(wrow);
            const ulonglong2 b1 = *(const ulonglong2*)(wrow + 4);
            u64 bp[4] = {b0.x, b0.y, b1.x, b1.y};
#pragma unroll
            for (int r = 0; r < 4; ++r) {
                float av = (k == 0) ? a4[r].x : (k == 1) ? a4[r].y
                         : (k == 2) ? a4[r].z : a4[r].w;
                u64 ap = pack2(av);
#pragma unroll
                for (int c = 0; c < 4; ++c)
                    ffma2(acc[r][c], ap, bp[c]);
            }
        }
    }
}

// Register prefetch of a 32x128 weight k-tile (16 floats / thread).
template<bool REMAP>
__device__ __forceinline__ void ldg_wt(float4 r[4], const float* __restrict__ W,
                                       int k0, int krows, int tid)
{
#pragma unroll
    for (int j = 0; j < 4; ++j) {
        int flat = (tid + j * 256) << 2;
        int kk = flat >> 7, c = flat & 127;
        int k = k0 + kk;
        if (REMAP) {
            int kr = (k < 256) ? k : k + 128;   // skip the 128-wide zero (mha) block
            r[j] = *(const float4*)(W + (size_t)kr * 128 + c);
        } else {
            r[j] = (k < krows) ? *(const float4*)(W + (size_t)k * 128 + c)
                               : make_float4(0.f, 0.f, 0.f, 0.f);
        }
    }
}

__device__ __forceinline__ void sts_wt(float* __restrict__ wt, const float4 r[4], int tid)
{
#pragma unroll
    for (int j = 0; j < 4; ++j)
        *(float4*)(wt + ((tid + j * 256) << 2)) = r[j];
}

// k-tiled GEMM with register-prefetched weight tiles (1 smem tile, LDG overlapped).
template<bool REMAP>
__device__ __forceinline__ void gemm_run(const float* __restrict__ A, int astride,
                                         const float* __restrict__ W, int krows, int ntiles,
                                         float* __restrict__ wt, int tid, int cb,
                                         u64 acc[4][4])
{
    float4 rw[4];
    ldg_wt<REMAP>(rw, W, 0, krows, tid);
#pragma unroll 1
    for (int t = 0; t < ntiles; ++t) {
        __syncthreads();                       // previous consumers of wt done
        sts_wt(wt, rw, tid);
        if (t + 1 < ntiles) ldg_wt<REMAP>(rw, W, (t + 1) * 32, krows, tid);
        __syncthreads();                       // wt tile ready
        gemm_tile(A + t * 32, astride, wt, cb, acc);
    }
}

__device__ __forceinline__ void zero_acc(u64 acc[4][4]) {
#pragma unroll
    for (int r = 0; r < 4; ++r)
#pragma unroll
        for (int c = 0; c < 4; ++c) acc[r][c] = 0ull;
}

__device__ __forceinline__ void acc_to_v(const u64 acc[4], float v[8]) {
#pragma unroll
    for (int c = 0; c < 4; ++c) {
        float2 f = unpack2(acc[c]);
        v[2 * c] = f.x; v[2 * c + 1] = f.y;
    }
}

// ---------------------------------------------------------------------------
// Edge kernel: 64 edges per block, 2 CTAs/SM.
// ---------------------------------------------------------------------------
__global__ __launch_bounds__(256, 2)
void edge_kernel(const float* __restrict__ feats, const float* __restrict__ x,
                 const float* __restrict__ edge_feats,
                 const int* __restrict__ src, const int* __restrict__ dst,
                 const float* __restrict__ eW1, const float* __restrict__ eb1,
                 const float* __restrict__ eg1, const float* __restrict__ ebn1,
                 const float* __restrict__ eW2, const float* __restrict__ eb2,
                 const float* __restrict__ cW1, const float* __restrict__ cb1,
                 const float* __restrict__ cW2, int E)
{
    extern __shared__ float sm[];
    float* ein  = sm;                        // 64 x 324
    float* wt   = ein + TILE * ESTRIDE;      // 32 x 128
    float* xr   = wt + 32 * 128;             // 64 x 3
    int*   sdst = (int*)(xr + TILE * 3);     // 64
    int*   ssrc = sdst + TILE;               // 64
    float* h1s  = ein;                       // overlay, 64 x 132
    float* ms   = ein + TILE * HSTRIDE;      // overlay, 64 x 132

    const int tid = threadIdx.x;
    const int e0 = blockIdx.x * TILE;

    if (tid < TILE) {
        int e = e0 + tid;
        int s = 0, d = 0;
        if (e < E) { s = src[e]; d = dst[e]; }
        ssrc[tid] = s; sdst[tid] = d;
    }
    __syncthreads();

    // Gather features (L2-resident table)
    for (int idx = tid; idx < TILE * HID; idx += 256) {
        int r = idx >> 7, c = idx & 127;
        ein[r * ESTRIDE + c]       = feats[(size_t)ssrc[r] * HID + c];
        ein[r * ESTRIDE + 128 + c] = feats[(size_t)sdst[r] * HID + c];
    }
    for (int idx = tid; idx < TILE * 32; idx += 256) {
        int r = idx >> 5, c = idx & 31;
        int e = e0 + r;
        ein[r * ESTRIDE + 256 + c] = (e < E) ? edge_feats[(size_t)e * 32 + c] : 0.f;
    }
    // Geometry + RBF
    if (tid < TILE) {
        int e = e0 + tid;
        float rx = 0.f, ry = 0.f, rz = 0.f;
        if (e < E) {
            int s = ssrc[tid], d = sdst[tid];
            rx = x[3 * s + 0] - x[3 * d + 0];
            ry = x[3 * s + 1] - x[3 * d + 1];
            rz = x[3 * s + 2] - x[3 * d + 2];
            float nrm = sqrtf(rx * rx + ry * ry + rz * rz) + 1.0f;
            float inv = 1.0f / nrm;
            rx *= inv; ry *= inv; rz *= inv;
        }
        xr[tid * 3 + 0] = rx; xr[tid * 3 + 1] = ry; xr[tid * 3 + 2] = rz;
        float d2 = rx * rx + ry * ry + rz * rz;
        float sig = 1.0f;
#pragma unroll
        for (int i = 0; i < 15; ++i) {
            ein[tid * ESTRIDE + 288 + i] = expf(-d2 / sig);
            sig *= 1.5f;
        }
#pragma unroll
        for (int i = 303; i < 320; ++i) ein[tid * ESTRIDE + i] = 0.f;
    }

    const int lane = tid & 31, warp = tid >> 5;
    const int rg = lane >> 4;
    const int r0 = warp * 8 + rg * 4;
    const int cb = (lane & 15) * 8;

    u64 acc[4][4];
    zero_acc(acc);

    // ---- GEMM1: e_in(320, 303 real) @ eW1 -> 128
    gemm_run<false>(ein + r0 * ESTRIDE, ESTRIDE, eW1, 303, 10, wt, tid, cb, acc);
    __syncthreads();   // all warps done reading ein before the h1s overlay write

    // ---- bias + lrelu + LayerNorm -> h1s (overlay)
    {
        float4 t0 = *(const float4*)(eb1 + cb), t1 = *(const float4*)(eb1 + cb + 4);
        float bb[8] = {t0.x, t0.y, t0.z, t0.w, t1.x, t1.y, t1.z, t1.w};
        float4 g0 = *(const float4*)(eg1 + cb), g1v = *(const float4*)(eg1 + cb + 4);
        float gg[8] = {g0.x, g0.y, g0.z, g0.w, g1v.x, g1v.y, g1v.z, g1v.w};
        float4 q0 = *(const float4*)(ebn1 + cb), q1 = *(const float4*)(ebn1 + cb + 4);
        float qq[8] = {q0.x, q0.y, q0.z, q0.w, q1.x, q1.y, q1.z, q1.w};
#pragma unroll
        for (int rr = 0; rr < 4; ++rr) {
            float v[8]; float s = 0.f, q = 0.f;
            acc_to_v(acc[rr], v);
#pragma unroll
            for (int c = 0; c < 8; ++c) {
                float t = lrelu(v[c] + bb[c]);
                v[c] = t; s += t; q += t * t;
            }
#pragma unroll
            for (int off = 8; off >= 1; off >>= 1) {
                s += __shfl_xor_sync(0xffffffffu, s, off);
                q += __shfl_xor_sync(0xffffffffu, q, off);
            }
            float mean = s * (1.f / 128.f);
            float var = q * (1.f / 128.f) - mean * mean;
            float inv = rsqrtf(var + 1e-5f);
            float* hp = h1s + (r0 + rr) * HSTRIDE + cb;
#pragma unroll
            for (int c = 0; c < 8; ++c)
                hp[c] = (v[c] - mean) * inv * gg[c] + qq[c];
        }
    }

    // ---- GEMM2: h1 @ eW2 -> m
    zero_acc(acc);
    gemm_run<false>(h1s + r0 * HSTRIDE, HSTRIDE, eW2, 128, 4, wt, tid, cb, acc);
    {
        float4 t0 = *(const float4*)(eb2 + cb), t1 = *(const float4*)(eb2 + cb + 4);
        float bb[8] = {t0.x, t0.y, t0.z, t0.w, t1.x, t1.y, t1.z, t1.w};
#pragma unroll
        for (int rr = 0; rr < 4; ++rr) {
            float v[8];
            acc_to_v(acc[rr], v);
            float* mp = ms + (r0 + rr) * HSTRIDE + cb;
#pragma unroll
            for (int c = 0; c < 8; ++c)
                mp[c] = lrelu(v[c] + bb[c]);
        }
    }

    // ---- GEMM3: t = lrelu(m @ cW1 + cb1); c = t @ cW2
    zero_acc(acc);
    gemm_run<false>(ms + r0 * HSTRIDE, HSTRIDE, cW1, 128, 4, wt, tid, cb, acc);

    float cv[4];
    {
        float4 t0 = *(const float4*)(cb1 + cb), t1 = *(const float4*)(cb1 + cb + 4);
        float bb[8] = {t0.x, t0.y, t0.z, t0.w, t1.x, t1.y, t1.z, t1.w};
        float4 w0 = *(const float4*)(cW2 + cb), w1 = *(const float4*)(cW2 + cb + 4);
        float ww[8] = {w0.x, w0.y, w0.z, w0.w, w1.x, w1.y, w1.z, w1.w};
#pragma unroll
        for (int rr = 0; rr < 4; ++rr) {
            float v[8];
            acc_to_v(acc[rr], v);
            float p = 0.f;
#pragma unroll
            for (int c = 0; c < 8; ++c)
                p += lrelu(v[c] + bb[c]) * ww[c];
#pragma unroll
            for (int off = 8; off >= 1; off >>= 1)
                p += __shfl_xor_sync(0xffffffffu, p, off);
            cv[rr] = p;
        }
    }

    // ---- Aggregation atomics
#pragma unroll
    for (int rr = 0; rr < 4; ++rr) {
        int row = r0 + rr;
        int e = e0 + row;
        if (e < E) {
            int dn = sdst[row];
            float* ab = g_aggr + (size_t)dn * 128 + cb;
            const float* mp = ms + row * HSTRIDE + cb;
#pragma unroll
            for (int c = 0; c < 8; ++c)
                atomicAdd(ab + c, mp[c]);
            if ((lane & 15) == rr) {
                atomicAdd(&g_xsum[(size_t)dn * 3 + 0], xr[row * 3 + 0] * cv[rr]);
                atomicAdd(&g_xsum[(size_t)dn * 3 + 1], xr[row * 3 + 1] * cv[rr]);
                atomicAdd(&g_xsum[(size_t)dn * 3 + 2], xr[row * 3 + 2] * cv[rr]);
                atomicAdd(&g_cnt[dn], 1.0f);
            }
        }
    }
}

// ---------------------------------------------------------------------------
// Node kernel: 64 nodes per block, 2 CTAs/SM.
// ---------------------------------------------------------------------------
__global__ __launch_bounds__(256, 2)
void node_kernel(const float* __restrict__ feats, const float* __restrict__ orig,
                 const float* __restrict__ x,
                 const float* __restrict__ nng, const float* __restrict__ nnb,
                 const float* __restrict__ nW1, const float* __restrict__ nb1,
                 const float* __restrict__ ng1, const float* __restrict__ nbn1,
                 const float* __restrict__ nW2, const float* __restrict__ nb2,
                 float* __restrict__ out, int N)
{
    extern __shared__ float sm[];
    float* nin = sm;                      // 64 x 324 (320 used)
    float* wt  = nin + TILE * ESTRIDE;    // 32 x 128
    float* nh  = nin;                     // overlay, 64 x 132

    const int tid = threadIdx.x;
    const int n0 = blockIdx.x * TILE;

    for (int idx = tid; idx < TILE * 128; idx += 256) {
        int r = idx >> 7, c = idx & 127;
        int n = n0 + r;
        nin[r * ESTRIDE + c]       = (n < N) ? feats[(size_t)n * 128 + c] : 0.f;
        nin[r * ESTRIDE + 128 + c] = (n < N) ? g_aggr[(size_t)n * 128 + c] : 0.f;
    }
    for (int idx = tid; idx < TILE * 64; idx += 256) {
        int r = idx >> 6, c = idx & 63;
        int n = n0 + r;
        nin[r * ESTRIDE + 256 + c] = (n < N) ? orig[(size_t)n * 64 + c] : 0.f;
    }
    __syncthreads();

    const int lane = tid & 31, warp = tid >> 5;
    const int rg = lane >> 4;
    const int r0 = warp * 8 + rg * 4;
    const int cb = (lane & 15) * 8;

    // LayerNorm(feats) in place on cols 0..127
    {
        float4 g0 = *(const float4*)(nng + cb), g1v = *(const float4*)(nng + cb + 4);
        float gg[8] = {g0.x, g0.y, g0.z, g0.w, g1v.x, g1v.y, g1v.z, g1v.w};
        float4 q0 = *(const float4*)(nnb + cb), q1 = *(const float4*)(nnb + cb + 4);
        float qq[8] = {q0.x, q0.y, q0.z, q0.w, q1.x, q1.y, q1.z, q1.w};
#pragma unroll
        for (int rr = 0; rr < 4; ++rr) {
            float* rp = nin + (r0 + rr) * ESTRIDE + cb;
            float v[8]; float s = 0.f, q = 0.f;
#pragma unroll
            for (int c = 0; c < 8; ++c) { v[c] = rp[c]; s += v[c]; q += v[c] * v[c]; }
#pragma unroll
            for (int off = 8; off >= 1; off >>= 1) {
                s += __shfl_xor_sync(0xffffffffu, s, off);
                q += __shfl_xor_sync(0xffffffffu, q, off);
            }
            float mean = s * (1.f / 128.f);
            float var = q * (1.f / 128.f) - mean * mean;
            float inv = rsqrtf(var + 1e-5f);
#pragma unroll
            for (int c = 0; c < 8; ++c)
                rp[c] = (v[c] - mean) * inv * gg[c] + qq[c];
        }
    }
    __syncthreads();

    u64 acc[4][4];
    zero_acc(acc);

    // GEMM1: 320-dim packed input; W1 rows remapped past the zero (mha) block
    gemm_run<true>(nin + r0 * ESTRIDE, ESTRIDE, nW1, 448, 10, wt, tid, cb, acc);
    __syncthreads();   // all warps done reading nin before the nh overlay write

    // bias + lrelu + LN -> nh (overlay)
    {
        float4 t0 = *(const float4*)(nb1 + cb), t1 = *(const float4*)(nb1 + cb + 4);
        float bb[8] = {t0.x, t0.y, t0.z, t0.w, t1.x, t1.y, t1.z, t1.w};
        float4 g0 = *(const float4*)(ng1 + cb), g1v = *(const float4*)(ng1 + cb + 4);
        float gg[8] = {g0.x, g0.y, g0.z, g0.w, g1v.x, g1v.y, g1v.z, g1v.w};
        float4 q0 = *(const float4*)(nbn1 + cb), q1 = *(const float4*)(nbn1 + cb + 4);
        float qq[8] = {q0.x, q0.y, q0.z, q0.w, q1.x, q1.y, q1.z, q1.w};
#pragma unroll
        for (int rr = 0; rr < 4; ++rr) {
            float v[8]; float s = 0.f, q = 0.f;
            acc_to_v(acc[rr], v);
#pragma unroll
            for (int c = 0; c < 8; ++c) {
                float t = lrelu(v[c] + bb[c]);
                v[c] = t; s += t; q += t * t;
            }
#pragma unroll
            for (int off = 8; off >= 1; off >>= 1) {
                s += __shfl_xor_sync(0xffffffffu, s, off);
                q += __shfl_xor_sync(0xffffffffu, q, off);
            }
            float mean = s * (1.f / 128.f);
            float var = q * (1.f / 128.f) - mean * mean;
            float inv = rsqrtf(var + 1e-5f);
            float* hp = nh + (r0 + rr) * HSTRIDE + cb;
#pragma unroll
            for (int c = 0; c < 8; ++c)
                hp[c] = (v[c] - mean) * inv * gg[c] + qq[c];
        }
    }

    // GEMM2: nh @ nW2
    zero_acc(acc);
    gemm_run<false>(nh + r0 * HSTRIDE, HSTRIDE, nW2, 128, 4, wt, tid, cb, acc);

    // Outputs
    {
        float4 t0 = *(const float4*)(nb2 + cb), t1 = *(const float4*)(nb2 + cb + 4);
        float bb[8] = {t0.x, t0.y, t0.z, t0.w, t1.x, t1.y, t1.z, t1.w};
#pragma unroll
        for (int rr = 0; rr < 4; ++rr) {
            int n = n0 + r0 + rr;
            if (n < N) {
                float v[8];
                acc_to_v(acc[rr], v);
                const float* fp = feats + (size_t)n * 128 + cb;
                float* op = out + (size_t)n * 128 + cb;
#pragma unroll
                for (int c = 0; c < 8; ++c) {
                    float o = v[c] + bb[c];
                    op[c] = 0.75f * o + 0.25f * fp[c];
                }
            }
        }
    }
    if (tid < TILE) {
        int n = n0 + tid;
        if (n < N) {
            float cnt = g_cnt[n];
            if (cnt < 1.f) cnt = 1.f;
            float inv = 1.f / cnt;
            size_t base = (size_t)N * 128 + (size_t)n * 3;
            out[base + 0] = x[(size_t)n * 3 + 0] + g_xsum[(size_t)n * 3 + 0] * inv;
            out[base + 1] = x[(size_t)n * 3 + 1] + g_xsum[(size_t)n * 3 + 1] * inv;
            out[base + 2] = x[(size_t)n * 3 + 2] + g_xsum[(size_t)n * 3 + 2] * inv;
        }
    }
}

extern "C" void kernel_launch(void* const* d_in, const int* in_sizes, int n_in,
                              void* d_out, int out_size)
{
    const float* feats      = (const float*)d_in[0];
    const float* orig       = (const float*)d_in[1];
    const float* x          = (const float*)d_in[2];
    /* d_in[3] = x_orig, unused (X_CONN_INIT = 0) */
    const float* edge_feats = (const float*)d_in[4];
    const int*   src        = (const int*)d_in[5];
    const int*   dst        = (const int*)d_in[6];
    const float* eW1  = (const float*)d_in[7];
    const float* eb1  = (const float*)d_in[8];
    const float* eg1  = (const float*)d_in[9];
    const float* ebn1 = (const float*)d_in[10];
    const float* eW2  = (const float*)d_in[11];
    const float* eb2  = (const float*)d_in[12];
    const float* nng  = (const float*)d_in[13];
    const float* nnb  = (const float*)d_in[14];
    const float* nW1  = (const float*)d_in[15];
    const float* nb1  = (const float*)d_in[16];
    const float* ng1  = (const float*)d_in[17];
    const float* nbn1 = (const float*)d_in[18];
    const float* nW2  = (const float*)d_in[19];
    const float* nb2  = (const float*)d_in[20];
    const float* cW1  = (const float*)d_in[21];
    const float* cb1  = (const float*)d_in[22];
    const float* cW2  = (const float*)d_in[23];

    const int N = in_sizes[0] / HID;
    const int E = in_sizes[5];

    void *aggr_p, *xs_p, *cnt_p;
    cudaGetSymbolAddress(&aggr_p, g_aggr);
    cudaGetSymbolAddress(&xs_p, g_xsum);
    cudaGetSymbolAddress(&cnt_p, g_cnt);
    cudaMemsetAsync(aggr_p, 0, (size_t)N * OUT * sizeof(float), 0);
    cudaMemsetAsync(xs_p, 0, (size_t)N * 3 * sizeof(float), 0);
    cudaMemsetAsync(cnt_p, 0, (size_t)N * sizeof(float), 0);

    const int SMEM_E = (TILE * ESTRIDE + 32 * 128 + TILE * 3) * 4
                       + TILE * 2 * (int)sizeof(int);              // ~100.6 KB
    const int SMEM_N = (TILE * ESTRIDE + 32 * 128) * 4;            // ~99.3 KB
    cudaFuncSetAttribute(edge_kernel, cudaFuncAttributeMaxDynamicSharedMemorySize, SMEM_E);
    cudaFuncSetAttribute(node_kernel, cudaFuncAttributeMaxDynamicSharedMemorySize, SMEM_N);

    int eblocks = (E + TILE - 1) / TILE;
    edge_kernel<<<eblocks, 256, SMEM_E>>>(feats, x, edge_feats, src, dst,
                                          eW1, eb1, eg1, ebn1, eW2, eb2,
                                          cW1, cb1, cW2, E);

    int nblocks = (N + TILE - 1) / TILE;
    node_kernel<<<nblocks, 256, SMEM_N>>>(feats, orig, x, nng, nnb,
                                          nW1, nb1, ng1, nbn1, nW2, nb2,
                                          (float*)d_out, N);
}

// round 6
// speedup vs baseline: 2.4718x; 1.5717x over previous
#include <cuda_runtime.h>
#include <math.h>

#define HID 128
#define OUT 128
#define NMAX 50000
#define ESTRIDE 324   // edge/node input stride (conflict-free A frags: 324%32==4)
#define HSTRIDE 132   // hidden buffer stride (132%32==4)
#define WSTRIDE 136   // weight tile stride (8k+col mod 32 unique -> conflict-free B frags)
#define KT 16         // weight k-tile rows
#define TILE 64

// Scratch (static __device__ globals; no allocations anywhere)
__device__ float g_aggr[(size_t)NMAX * OUT];
__device__ float g_xsum[(size_t)NMAX * 3];
__device__ float g_cnt[NMAX];

__device__ __forceinline__ float lrelu(float v) { return v > 0.f ? v : 0.01f * v; }

// ---------------- tf32 split helpers ----------------
__device__ __forceinline__ unsigned tf32_rna(float v) {
    unsigned r;
    asm("cvt.rna.tf32.f32 %0, %1;" : "=r"(r) : "f"(v));
    return r;
}
__device__ __forceinline__ void split_tf32(float v, unsigned& hi, unsigned& lo) {
    hi = tf32_rna(v);
    lo = tf32_rna(v - __uint_as_float(hi));
}
// m16n8k8 tf32 MMA, C += A*B
__device__ __forceinline__ void mma8(float c[4], const unsigned a[4], unsigned b0, unsigned b1) {
    asm("mma.sync.aligned.m16n8k8.row.col.f32.tf32.tf32.f32 "
        "{%0,%1,%2,%3}, {%4,%5,%6,%7}, {%8,%9}, {%0,%1,%2,%3};"
        : "+f"(c[0]), "+f"(c[1]), "+f"(c[2]), "+f"(c[3])
        : "r"(a[0]), "r"(a[1]), "r"(a[2]), "r"(a[3]), "r"(b0), "r"(b1));
}

// ---------------- weight tile producer (16x128, split hi/lo into smem) ----------------
__device__ __forceinline__ void ldg_w16(float4 rw[2], const float* __restrict__ W,
                                        int k0, int krows, int tid)
{
    int k = k0 + (tid >> 4);
    int c = (tid & 15) * 8;
    if (k < krows) {
        rw[0] = *(const float4*)(W + (size_t)k * 128 + c);
        rw[1] = *(const float4*)(W + (size_t)k * 128 + c + 4);
    } else {
        rw[0] = make_float4(0.f, 0.f, 0.f, 0.f);
        rw[1] = make_float4(0.f, 0.f, 0.f, 0.f);
    }
}
__device__ __forceinline__ void sts_w16(float* __restrict__ wh, float* __restrict__ wl,
                                        const float4 rw[2], int tid)
{
    int k = tid >> 4, c = (tid & 15) * 8;
    float v[8] = {rw[0].x, rw[0].y, rw[0].z, rw[0].w, rw[1].x, rw[1].y, rw[1].z, rw[1].w};
    float h[8], l[8];
#pragma unroll
    for (int i = 0; i < 8; ++i) {
        unsigned hb, lb;
        split_tf32(v[i], hb, lb);
        h[i] = __uint_as_float(hb);
        l[i] = __uint_as_float(lb);
    }
    *(float4*)(wh + k * WSTRIDE + c)     = make_float4(h[0], h[1], h[2], h[3]);
    *(float4*)(wh + k * WSTRIDE + c + 4) = make_float4(h[4], h[5], h[6], h[7]);
    *(float4*)(wl + k * WSTRIDE + c)     = make_float4(l[0], l[1], l[2], l[3]);
    *(float4*)(wl + k * WSTRIDE + c + 4) = make_float4(l[4], l[5], l[6], l[7]);
}

// ---------------- warp-level split-tf32 GEMM ----------------
// Accumulates A[rbase..rbase+15, 0..ntiles*KT) @ W[k, cbase..cbase+63] into c[8][4].
__device__ __forceinline__ void gemm_mma(const float* __restrict__ As, int astride,
                                         const float* __restrict__ W, int krows, int ntiles,
                                         float* __restrict__ wh, float* __restrict__ wl,
                                         int tid, int rbase, int cbase, int gid, int tg,
                                         float c[8][4])
{
    float4 rw[2];
    ldg_w16(rw, W, 0, krows, tid);
    const float* Ar1 = As + (size_t)(rbase + gid) * astride;
    const float* Ar2 = As + (size_t)(rbase + gid + 8) * astride;
#pragma unroll 1
    for (int t = 0; t < ntiles; ++t) {
        __syncthreads();                       // prior consumers of wh/wl done
        sts_w16(wh, wl, rw, tid);
        if (t + 1 < ntiles) ldg_w16(rw, W, (t + 1) * KT, krows, tid);
        __syncthreads();                       // tile ready
#pragma unroll
        for (int ks = 0; ks < 2; ++ks) {
            int kA = t * KT + ks * 8 + tg;
            unsigned ahi[4], alo[4];
            split_tf32(Ar1[kA],     ahi[0], alo[0]);
            split_tf32(Ar2[kA],     ahi[1], alo[1]);
            split_tf32(Ar1[kA + 4], ahi[2], alo[2]);
            split_tf32(Ar2[kA + 4], ahi[3], alo[3]);
            const float* whb = wh + (ks * 8 + tg) * WSTRIDE;
            const float* wlb = wl + (ks * 8 + tg) * WSTRIDE;
#pragma unroll
            for (int nt = 0; nt < 8; ++nt) {
                int coln = cbase + nt * 8 + gid;
                unsigned bh0 = __float_as_uint(whb[coln]);
                unsigned bh1 = __float_as_uint(whb[4 * WSTRIDE + coln]);
                unsigned bl0 = __float_as_uint(wlb[coln]);
                unsigned bl1 = __float_as_uint(wlb[4 * WSTRIDE + coln]);
                mma8(c[nt], ahi, bh0, bh1);
                mma8(c[nt], alo, bh0, bh1);
                mma8(c[nt], ahi, bl0, bl1);
            }
        }
    }
}

__device__ __forceinline__ void zero_c(float c[8][4]) {
#pragma unroll
    for (int i = 0; i < 8; ++i)
#pragma unroll
        for (int j = 0; j < 4; ++j) c[i][j] = 0.f;
}

// ---------------------------------------------------------------------------
// Edge kernel (tensor-core path): 64 edges per block, 2 CTAs/SM.
// ---------------------------------------------------------------------------
__global__ __launch_bounds__(256, 2)
void edge_kernel(const float* __restrict__ feats, const float* __restrict__ x,
                 const float* __restrict__ edge_feats,
                 const int* __restrict__ src, const int* __restrict__ dst,
                 const float* __restrict__ eW1, const float* __restrict__ eb1,
                 const float* __restrict__ eg1, const float* __restrict__ ebn1,
                 const float* __restrict__ eW2, const float* __restrict__ eb2,
                 const float* __restrict__ cW1, const float* __restrict__ cb1,
                 const float* __restrict__ cW2, int E)
{
    extern __shared__ float sm[];
    float*  ein   = sm;                          // 64 x 324
    float*  wh    = ein + TILE * ESTRIDE;        // 16 x 136
    float*  wl    = wh + KT * WSTRIDE;           // 16 x 136
    float*  xr    = wl + KT * WSTRIDE;           // 64 x 3
    float2* red   = (float2*)(xr + TILE * 3);    // [64][2] (sum,sumsq) per half
    float*  cvred = (float*)(red + TILE * 2);    // [64][2]
    int*    sdst  = (int*)(cvred + TILE * 2);    // 64
    int*    ssrc  = sdst + TILE;                 // 64
    float*  h1s   = ein;                         // overlay, 64 x 132
    float*  ms    = ein + TILE * HSTRIDE;        // overlay, 64 x 132

    const int tid = threadIdx.x;
    const int e0 = blockIdx.x * TILE;

    if (tid < TILE) {
        int e = e0 + tid;
        int s = 0, d = 0;
        if (e < E) { s = src[e]; d = dst[e]; }
        ssrc[tid] = s; sdst[tid] = d;
    }
    __syncthreads();

    // Gather features (L2-resident table)
    for (int idx = tid; idx < TILE * HID; idx += 256) {
        int r = idx >> 7, c = idx & 127;
        ein[r * ESTRIDE + c]       = feats[(size_t)ssrc[r] * HID + c];
        ein[r * ESTRIDE + 128 + c] = feats[(size_t)sdst[r] * HID + c];
    }
    for (int idx = tid; idx < TILE * 32; idx += 256) {
        int r = idx >> 5, c = idx & 31;
        int e = e0 + r;
        ein[r * ESTRIDE + 256 + c] = (e < E) ? edge_feats[(size_t)e * 32 + c] : 0.f;
    }
    // Geometry + RBF
    if (tid < TILE) {
        int e = e0 + tid;
        float rx = 0.f, ry = 0.f, rz = 0.f;
        if (e < E) {
            int s = ssrc[tid], d = sdst[tid];
            rx = x[3 * s + 0] - x[3 * d + 0];
            ry = x[3 * s + 1] - x[3 * d + 1];
            rz = x[3 * s + 2] - x[3 * d + 2];
            float nrm = sqrtf(rx * rx + ry * ry + rz * rz) + 1.0f;
            float inv = 1.0f / nrm;
            rx *= inv; ry *= inv; rz *= inv;
        }
        xr[tid * 3 + 0] = rx; xr[tid * 3 + 1] = ry; xr[tid * 3 + 2] = rz;
        float d2 = rx * rx + ry * ry + rz * rz;
        float sig = 1.0f;
#pragma unroll
        for (int i = 0; i < 15; ++i) {
            ein[tid * ESTRIDE + 288 + i] = expf(-d2 / sig);
            sig *= 1.5f;
        }
#pragma unroll
        for (int i = 303; i < 320; ++i) ein[tid * ESTRIDE + i] = 0.f;
    }
    // (gemm_mma's first __syncthreads orders the gather writes before MMA reads)

    const int lane = tid & 31, warp = tid >> 5;
    const int gid = lane >> 2, tg = lane & 3;
    const int rbase = (warp & 3) * 16;
    const int cbase = (warp >> 2) * 64;
    const int half = warp >> 2;
    const int r1 = rbase + gid, r2 = r1 + 8;

    float c[8][4];

    // ---- GEMM1: e_in(320, 303 real) @ eW1 -> 128
    zero_c(c);
    gemm_mma(ein, ESTRIDE, eW1, 303, 20, wh, wl, tid, rbase, cbase, gid, tg, c);

    // ---- bias + lrelu + LayerNorm -> h1s (overlay on ein)
    {
        float s1 = 0.f, q1 = 0.f, s2 = 0.f, q2 = 0.f;
#pragma unroll
        for (int nt = 0; nt < 8; ++nt) {
            int col = cbase + nt * 8 + 2 * tg;
            float2 b = *(const float2*)(eb1 + col);
            float t00 = lrelu(c[nt][0] + b.x), t01 = lrelu(c[nt][1] + b.y);
            float t10 = lrelu(c[nt][2] + b.x), t11 = lrelu(c[nt][3] + b.y);
            c[nt][0] = t00; c[nt][1] = t01; c[nt][2] = t10; c[nt][3] = t11;
            s1 += t00 + t01; q1 += t00 * t00 + t01 * t01;
            s2 += t10 + t11; q2 += t10 * t10 + t11 * t11;
        }
#pragma unroll
        for (int off = 1; off <= 2; off <<= 1) {
            s1 += __shfl_xor_sync(0xffffffffu, s1, off);
            q1 += __shfl_xor_sync(0xffffffffu, q1, off);
            s2 += __shfl_xor_sync(0xffffffffu, s2, off);
            q2 += __shfl_xor_sync(0xffffffffu, q2, off);
        }
        if (tg == 0) {
            red[r1 * 2 + half] = make_float2(s1, q1);
            red[r2 * 2 + half] = make_float2(s2, q2);
        }
        __syncthreads();   // red visible; also: all warps done reading ein -> overlay safe
        float2 u = red[r1 * 2 + 0], v = red[r1 * 2 + 1];
        float m1 = (u.x + v.x) * (1.f / 128.f);
        float inv1 = rsqrtf((u.y + v.y) * (1.f / 128.f) - m1 * m1 + 1e-5f);
        u = red[r2 * 2 + 0]; v = red[r2 * 2 + 1];
        float m2 = (u.x + v.x) * (1.f / 128.f);
        float inv2 = rsqrtf((u.y + v.y) * (1.f / 128.f) - m2 * m2 + 1e-5f);
#pragma unroll
        for (int nt = 0; nt < 8; ++nt) {
            int col = cbase + nt * 8 + 2 * tg;
            float2 g = *(const float2*)(eg1 + col);
            float2 bt = *(const float2*)(ebn1 + col);
            *(float2*)(h1s + r1 * HSTRIDE + col) =
                make_float2((c[nt][0] - m1) * inv1 * g.x + bt.x,
                            (c[nt][1] - m1) * inv1 * g.y + bt.y);
            *(float2*)(h1s + r2 * HSTRIDE + col) =
                make_float2((c[nt][2] - m2) * inv2 * g.x + bt.x,
                            (c[nt][3] - m2) * inv2 * g.y + bt.y);
        }
    }

    // ---- GEMM2: h1 @ eW2 -> m (lrelu) -> ms
    zero_c(c);
    gemm_mma(h1s, HSTRIDE, eW2, 128, 8, wh, wl, tid, rbase, cbase, gid, tg, c);
    {
#pragma unroll
        for (int nt = 0; nt < 8; ++nt) {
            int col = cbase + nt * 8 + 2 * tg;
            float2 b = *(const float2*)(eb2 + col);
            *(float2*)(ms + r1 * HSTRIDE + col) =
                make_float2(lrelu(c[nt][0] + b.x), lrelu(c[nt][1] + b.y));
            *(float2*)(ms + r2 * HSTRIDE + col) =
                make_float2(lrelu(c[nt][2] + b.x), lrelu(c[nt][3] + b.y));
        }
    }

    // ---- GEMM3: t = lrelu(m @ cW1 + cb1); c_coef = t . cW2
    zero_c(c);
    gemm_mma(ms, HSTRIDE, cW1, 128, 8, wh, wl, tid, rbase, cbase, gid, tg, c);
    {
        float p1 = 0.f, p2 = 0.f;
#pragma unroll
        for (int nt = 0; nt < 8; ++nt) {
            int col = cbase + nt * 8 + 2 * tg;
            float2 b = *(const float2*)(cb1 + col);
            float2 w = *(const float2*)(cW2 + col);
            p1 += lrelu(c[nt][0] + b.x) * w.x + lrelu(c[nt][1] + b.y) * w.y;
            p2 += lrelu(c[nt][2] + b.x) * w.x + lrelu(c[nt][3] + b.y) * w.y;
        }
#pragma unroll
        for (int off = 1; off <= 2; off <<= 1) {
            p1 += __shfl_xor_sync(0xffffffffu, p1, off);
            p2 += __shfl_xor_sync(0xffffffffu, p2, off);
        }
        if (tg == 0) {
            cvred[r1 * 2 + half] = p1;
            cvred[r2 * 2 + half] = p2;
        }
    }
    __syncthreads();

    // ---- Aggregation atomics (coalesced REDs over ms)
    for (int idx = tid; idx < TILE * 128; idx += 256) {
        int row = idx >> 7, col = idx & 127;
        int e = e0 + row;
        if (e < E)
            atomicAdd(g_aggr + (size_t)sdst[row] * 128 + col, ms[row * HSTRIDE + col]);
    }
    if (tid < TILE) {
        int e = e0 + tid;
        if (e < E) {
            float cv = cvred[tid * 2] + cvred[tid * 2 + 1];
            int dn = sdst[tid];
            atomicAdd(&g_xsum[(size_t)dn * 3 + 0], xr[tid * 3 + 0] * cv);
            atomicAdd(&g_xsum[(size_t)dn * 3 + 1], xr[tid * 3 + 1] * cv);
            atomicAdd(&g_xsum[(size_t)dn * 3 + 2], xr[tid * 3 + 2] * cv);
            atomicAdd(&g_cnt[dn], 1.0f);
        }
    }
}

// ===========================================================================
// Node kernel: unchanged SIMT f32x2 path (265us; not the bottleneck).
// ===========================================================================
typedef unsigned long long u64;

__device__ __forceinline__ u64 pack2(float v) {
    u64 p; asm("mov.b64 %0, {%1, %1};" : "=l"(p) : "f"(v)); return p;
}
__device__ __forceinline__ float2 unpack2(u64 v) {
    float2 f; asm("mov.b64 {%0, %1}, %2;" : "=f"(f.x), "=f"(f.y) : "l"(v)); return f;
}
__device__ __forceinline__ void ffma2(u64& d, u64 a, u64 b) {
    asm("fma.rn.f32x2 %0, %1, %2, %0;" : "+l"(d) : "l"(a), "l"(b));
}

__device__ __forceinline__ void gemm_tile_s(const float* __restrict__ A, int astride,
                                            const float* __restrict__ wt, int cb,
                                            u64 acc[4][4])
{
#pragma unroll
    for (int kq = 0; kq < 8; ++kq) {
        float4 a4[4];
#pragma unroll
        for (int r = 0; r < 4; ++r)
            a4[r] = *(const float4*)(A + r * astride + kq * 4);
#pragma unroll
        for (int k = 0; k < 4; ++k) {
            const float* wrow = wt + (kq * 4 + k) * 128 + cb;
            const ulonglong2 b0 = *(const ulonglong2*)(wrow);
            const ulonglong2 b1 = *(const ulonglong2*)(wrow + 4);
            u64 bp[4] = {b0.x, b0.y, b1.x, b1.y};
#pragma unroll
            for (int r = 0; r < 4; ++r) {
                float av = (k == 0) ? a4[r].x : (k == 1) ? a4[r].y
                         : (k == 2) ? a4[r].z : a4[r].w;
                u64 ap = pack2(av);
#pragma unroll
                for (int c = 0; c < 4; ++c)
                    ffma2(acc[r][c], ap, bp[c]);
            }
        }
    }
}

template<bool REMAP>
__device__ __forceinline__ void ldg_wt(float4 r[4], const float* __restrict__ W,
                                       int k0, int krows, int tid)
{
#pragma unroll
    for (int j = 0; j < 4; ++j) {
        int flat = (tid + j * 256) << 2;
        int kk = flat >> 7, c2 = flat & 127;
        int k = k0 + kk;
        if (REMAP) {
            int kr = (k < 256) ? k : k + 128;
            r[j] = *(const float4*)(W + (size_t)kr * 128 + c2);
        } else {
            r[j] = (k < krows) ? *(const float4*)(W + (size_t)k * 128 + c2)
                               : make_float4(0.f, 0.f, 0.f, 0.f);
        }
    }
}
__device__ __forceinline__ void sts_wt(float* __restrict__ wt, const float4 r[4], int tid)
{
#pragma unroll
    for (int j = 0; j < 4; ++j)
        *(float4*)(wt + ((tid + j * 256) << 2)) = r[j];
}
template<bool REMAP>
__device__ __forceinline__ void gemm_run(const float* __restrict__ A, int astride,
                                         const float* __restrict__ W, int krows, int ntiles,
                                         float* __restrict__ wt, int tid, int cb,
                                         u64 acc[4][4])
{
    float4 rw[4];
    ldg_wt<REMAP>(rw, W, 0, krows, tid);
#pragma unroll 1
    for (int t = 0; t < ntiles; ++t) {
        __syncthreads();
        sts_wt(wt, rw, tid);
        if (t + 1 < ntiles) ldg_wt<REMAP>(rw, W, (t + 1) * 32, krows, tid);
        __syncthreads();
        gemm_tile_s(A + t * 32, astride, wt, cb, acc);
    }
}
__device__ __forceinline__ void zero_acc(u64 acc[4][4]) {
#pragma unroll
    for (int r = 0; r < 4; ++r)
#pragma unroll
        for (int c = 0; c < 4; ++c) acc[r][c] = 0ull;
}
__device__ __forceinline__ void acc_to_v(const u64 acc[4], float v[8]) {
#pragma unroll
    for (int c = 0; c < 4; ++c) {
        float2 f = unpack2(acc[c]);
        v[2 * c] = f.x; v[2 * c + 1] = f.y;
    }
}

__global__ __launch_bounds__(256, 2)
void node_kernel(const float* __restrict__ feats, const float* __restrict__ orig,
                 const float* __restrict__ x,
                 const float* __restrict__ nng, const float* __restrict__ nnb,
                 const float* __restrict__ nW1, const float* __restrict__ nb1,
                 const float* __restrict__ ng1, const float* __restrict__ nbn1,
                 const float* __restrict__ nW2, const float* __restrict__ nb2,
                 float* __restrict__ out, int N)
{
    extern __shared__ float sm[];
    float* nin = sm;                      // 64 x 324 (320 used)
    float* wt  = nin + TILE * ESTRIDE;    // 32 x 128
    float* nh  = nin;                     // overlay, 64 x 132

    const int tid = threadIdx.x;
    const int n0 = blockIdx.x * TILE;

    for (int idx = tid; idx < TILE * 128; idx += 256) {
        int r = idx >> 7, c = idx & 127;
        int n = n0 + r;
        nin[r * ESTRIDE + c]       = (n < N) ? feats[(size_t)n * 128 + c] : 0.f;
        nin[r * ESTRIDE + 128 + c] = (n < N) ? g_aggr[(size_t)n * 128 + c] : 0.f;
    }
    for (int idx = tid; idx < TILE * 64; idx += 256) {
        int r = idx >> 6, c = idx & 63;
        int n = n0 + r;
        nin[r * ESTRIDE + 256 + c] = (n < N) ? orig[(size_t)n * 64 + c] : 0.f;
    }
    __syncthreads();

    const int lane = tid & 31, warp = tid >> 5;
    const int rg = lane >> 4;
    const int r0 = warp * 8 + rg * 4;
    const int cb = (lane & 15) * 8;

    {
        float4 g0 = *(const float4*)(nng + cb), g1v = *(const float4*)(nng + cb + 4);
        float gg[8] = {g0.x, g0.y, g0.z, g0.w, g1v.x, g1v.y, g1v.z, g1v.w};
        float4 q0 = *(const float4*)(nnb + cb), q1 = *(const float4*)(nnb + cb + 4);
        float qq[8] = {q0.x, q0.y, q0.z, q0.w, q1.x, q1.y, q1.z, q1.w};
#pragma unroll
        for (int rr = 0; rr < 4; ++rr) {
            float* rp = nin + (r0 + rr) * ESTRIDE + cb;
            float v[8]; float s = 0.f, q = 0.f;
#pragma unroll
            for (int c = 0; c < 8; ++c) { v[c] = rp[c]; s += v[c]; q += v[c] * v[c]; }
#pragma unroll
            for (int off = 8; off >= 1; off >>= 1) {
                s += __shfl_xor_sync(0xffffffffu, s, off);
                q += __shfl_xor_sync(0xffffffffu, q, off);
            }
            float mean = s * (1.f / 128.f);
            float var = q * (1.f / 128.f) - mean * mean;
            float inv = rsqrtf(var + 1e-5f);
#pragma unroll
            for (int c = 0; c < 8; ++c)
                rp[c] = (v[c] - mean) * inv * gg[c] + qq[c];
        }
    }
    __syncthreads();

    u64 acc[4][4];
    zero_acc(acc);
    gemm_run<true>(nin + r0 * ESTRIDE, ESTRIDE, nW1, 448, 10, wt, tid, cb, acc);
    __syncthreads();

    {
        float4 t0 = *(const float4*)(nb1 + cb), t1 = *(const float4*)(nb1 + cb + 4);
        float bb[8] = {t0.x, t0.y, t0.z, t0.w, t1.x, t1.y, t1.z, t1.w};
        float4 g0 = *(const float4*)(ng1 + cb), g1v = *(const float4*)(ng1 + cb + 4);
        float gg[8] = {g0.x, g0.y, g0.z, g0.w, g1v.x, g1v.y, g1v.z, g1v.w};
        float4 q0 = *(const float4*)(nbn1 + cb), q1 = *(const float4*)(nbn1 + cb + 4);
        float qq[8] = {q0.x, q0.y, q0.z, q0.w, q1.x, q1.y, q1.z, q1.w};
#pragma unroll
        for (int rr = 0; rr < 4; ++rr) {
            float v[8]; float s = 0.f, q = 0.f;
            acc_to_v(acc[rr], v);
#pragma unroll
            for (int c = 0; c < 8; ++c) {
                float t = lrelu(v[c] + bb[c]);
                v[c] = t; s += t; q += t * t;
            }
#pragma unroll
            for (int off = 8; off >= 1; off >>= 1) {
                s += __shfl_xor_sync(0xffffffffu, s, off);
                q += __shfl_xor_sync(0xffffffffu, q, off);
            }
            float mean = s * (1.f / 128.f);
            float var = q * (1.f / 128.f) - mean * mean;
            float inv = rsqrtf(var + 1e-5f);
            float* hp = nh + (r0 + rr) * HSTRIDE + cb;
#pragma unroll
            for (int c = 0; c < 8; ++c)
                hp[c] = (v[c] - mean) * inv * gg[c] + qq[c];
        }
    }

    zero_acc(acc);
    gemm_run<false>(nh + r0 * HSTRIDE, HSTRIDE, nW2, 128, 4, wt, tid, cb, acc);

    {
        float4 t0 = *(const float4*)(nb2 + cb), t1 = *(const float4*)(nb2 + cb + 4);
        float bb[8] = {t0.x, t0.y, t0.z, t0.w, t1.x, t1.y, t1.z, t1.w};
#pragma unroll
        for (int rr = 0; rr < 4; ++rr) {
            int n = n0 + r0 + rr;
            if (n < N) {
                float v[8];
                acc_to_v(acc[rr], v);
                const float* fp = feats + (size_t)n * 128 + cb;
                float* op = out + (size_t)n * 128 + cb;
#pragma unroll
                for (int c = 0; c < 8; ++c) {
                    float o = v[c] + bb[c];
                    op[c] = 0.75f * o + 0.25f * fp[c];
                }
            }
        }
    }
    if (tid < TILE) {
        int n = n0 + tid;
        if (n < N) {
            float cnt = g_cnt[n];
            if (cnt < 1.f) cnt = 1.f;
            float inv = 1.f / cnt;
            size_t base = (size_t)N * 128 + (size_t)n * 3;
            out[base + 0] = x[(size_t)n * 3 + 0] + g_xsum[(size_t)n * 3 + 0] * inv;
            out[base + 1] = x[(size_t)n * 3 + 1] + g_xsum[(size_t)n * 3 + 1] * inv;
            out[base + 2] = x[(size_t)n * 3 + 2] + g_xsum[(size_t)n * 3 + 2] * inv;
        }
    }
}

extern "C" void kernel_launch(void* const* d_in, const int* in_sizes, int n_in,
                              void* d_out, int out_size)
{
    const float* feats      = (const float*)d_in[0];
    const float* orig       = (const float*)d_in[1];
    const float* x          = (const float*)d_in[2];
    /* d_in[3] = x_orig, unused (X_CONN_INIT = 0) */
    const float* edge_feats = (const float*)d_in[4];
    const int*   src        = (const int*)d_in[5];
    const int*   dst        = (const int*)d_in[6];
    const float* eW1  = (const float*)d_in[7];
    const float* eb1  = (const float*)d_in[8];
    const float* eg1  = (const float*)d_in[9];
    const float* ebn1 = (const float*)d_in[10];
    const float* eW2  = (const float*)d_in[11];
    const float* eb2  = (const float*)d_in[12];
    const float* nng  = (const float*)d_in[13];
    const float* nnb  = (const float*)d_in[14];
    const float* nW1  = (const float*)d_in[15];
    const float* nb1  = (const float*)d_in[16];
    const float* ng1  = (const float*)d_in[17];
    const float* nbn1 = (const float*)d_in[18];
    const float* nW2  = (const float*)d_in[19];
    const float* nb2  = (const float*)d_in[20];
    const float* cW1  = (const float*)d_in[21];
    const float* cb1  = (const float*)d_in[22];
    const float* cW2  = (const float*)d_in[23];

    const int N = in_sizes[0] / HID;
    const int E = in_sizes[5];

    void *aggr_p, *xs_p, *cnt_p;
    cudaGetSymbolAddress(&aggr_p, g_aggr);
    cudaGetSymbolAddress(&xs_p, g_xsum);
    cudaGetSymbolAddress(&cnt_p, g_cnt);
    cudaMemsetAsync(aggr_p, 0, (size_t)N * OUT * sizeof(float), 0);
    cudaMemsetAsync(xs_p, 0, (size_t)N * 3 * sizeof(float), 0);
    cudaMemsetAsync(cnt_p, 0, (size_t)N * sizeof(float), 0);

    // edge smem: ein + 2 weight tiles + xr + red + cvred + idx
    const int SMEM_E = (TILE * ESTRIDE + 2 * KT * WSTRIDE + TILE * 3
                        + TILE * 2 * 2 + TILE * 2) * 4
                       + TILE * 2 * (int)sizeof(int);
    const int SMEM_N = (TILE * ESTRIDE + 32 * 128) * 4;
    cudaFuncSetAttribute(edge_kernel, cudaFuncAttributeMaxDynamicSharedMemorySize, SMEM_E);
    cudaFuncSetAttribute(node_kernel, cudaFuncAttributeMaxDynamicSharedMemorySize, SMEM_N);

    int eblocks = (E + TILE - 1) / TILE;
    edge_kernel<<<eblocks, 256, SMEM_E>>>(feats, x, edge_feats, src, dst,
                                          eW1, eb1, eg1, ebn1, eW2, eb2,
                                          cW1, cb1, cW2, E);

    int nblocks = (N + TILE - 1) / TILE;
    node_kernel<<<nblocks, 256, SMEM_N>>>(feats, orig, x, nng, nnb,
                                          nW1, nb1, ng1, nbn1, nW2, nb2,
                                          (float*)d_out, N);
}

// round 7
// speedup vs baseline: 3.4427x; 1.3928x over previous
#include <cuda_runtime.h>
#include <cuda_bf16.h>
#include <math.h>

#define HID 128
#define OUT 128
#define NMAX 50000
#define ESTRIDE 324   // edge/node input stride
#define HSTRIDE 132   // hidden buffer stride
#define WSTRIDE 136   // packed-weight tile stride in u32 (conflict-free B frags)
#define KT 16         // k-tile rows (one m16n8k16 chunk)
#define TILE 64

// Scratch (static __device__ globals; no allocations anywhere)
__device__ float g_aggr[(size_t)NMAX * OUT];
__device__ float g_xsum[(size_t)NMAX * 3];
__device__ float g_cnt[NMAX];

__device__ __forceinline__ float lrelu(float v) { return v > 0.f ? v : 0.01f * v; }

// ---------------- bf16 split helpers ----------------
// pack two floats to bf16x2: low half <- a, high half <- b
__device__ __forceinline__ unsigned bf16x2_pack(float a, float b) {
    unsigned r;
    asm("cvt.rn.bf16x2.f32 %0, %1, %2;" : "=r"(r) : "f"(b), "f"(a));
    return r;
}
__device__ __forceinline__ float bf16_lo_f(unsigned p) { return __uint_as_float(p << 16); }
__device__ __forceinline__ float bf16_hi_f(unsigned p) { return __uint_as_float(p & 0xffff0000u); }

// split a float2 (consecutive k) into hi/lo bf16x2 words
__device__ __forceinline__ void split2(float2 a, unsigned& hi, unsigned& lo) {
    hi = bf16x2_pack(a.x, a.y);
    float r0 = a.x - bf16_lo_f(hi);
    float r1 = a.y - bf16_hi_f(hi);
    lo = bf16x2_pack(r0, r1);
}

// m16n8k16 bf16 MMA, C += A*B
__device__ __forceinline__ void mma16(float c[4], const unsigned a[4], unsigned b0, unsigned b1) {
    asm("mma.sync.aligned.m16n8k16.row.col.f32.bf16.bf16.f32 "
        "{%0,%1,%2,%3}, {%4,%5,%6,%7}, {%8,%9}, {%0,%1,%2,%3};"
        : "+f"(c[0]), "+f"(c[1]), "+f"(c[2]), "+f"(c[3])
        : "r"(a[0]), "r"(a[1]), "r"(a[2]), "r"(a[3]), "r"(b0), "r"(b1));
}

// ---------------- weight tile producer (16x128 fp32 -> packed bf16 hi/lo) ----
// thread t: k-pair p = t>>5 (0..7), cols c..c+3 = (t&31)*4
__device__ __forceinline__ void ldg_w16(float4 rw[2], const float* __restrict__ W,
                                        int k0, int krows, int tid)
{
    int p = tid >> 5;
    int c = (tid & 31) * 4;
    int k = k0 + 2 * p;
    rw[0] = (k < krows)     ? *(const float4*)(W + (size_t)k * 128 + c)
                            : make_float4(0.f, 0.f, 0.f, 0.f);
    rw[1] = (k + 1 < krows) ? *(const float4*)(W + (size_t)(k + 1) * 128 + c)
                            : make_float4(0.f, 0.f, 0.f, 0.f);
}
__device__ __forceinline__ void sts_w16(unsigned* __restrict__ whp, unsigned* __restrict__ wlp,
                                        const float4 rw[2], int tid)
{
    int p = tid >> 5, c = (tid & 31) * 4;
    float a0[4] = {rw[0].x, rw[0].y, rw[0].z, rw[0].w};
    float a1[4] = {rw[1].x, rw[1].y, rw[1].z, rw[1].w};
    unsigned h[4], l[4];
#pragma unroll
    for (int i = 0; i < 4; ++i) {
        h[i] = bf16x2_pack(a0[i], a1[i]);           // {k, k+1}
        float r0 = a0[i] - bf16_lo_f(h[i]);
        float r1 = a1[i] - bf16_hi_f(h[i]);
        l[i] = bf16x2_pack(r0, r1);
    }
    *(uint4*)(whp + p * WSTRIDE + c) = make_uint4(h[0], h[1], h[2], h[3]);
    *(uint4*)(wlp + p * WSTRIDE + c) = make_uint4(l[0], l[1], l[2], l[3]);
}

// ---------------- warp-level split-bf16 GEMM ----------------
// Accumulates A[rbase..rbase+15, :] @ W[:, cbase..cbase+63] into c[8][4].
__device__ __forceinline__ void gemm_mma(const float* __restrict__ As, int astride,
                                         const float* __restrict__ W, int krows, int ntiles,
                                         unsigned* __restrict__ whp, unsigned* __restrict__ wlp,
                                         int tid, int rbase, int cbase, int gid, int tg,
                                         float c[8][4])
{
    float4 rw[2];
    ldg_w16(rw, W, 0, krows, tid);
    const float* Ar1 = As + (size_t)(rbase + gid) * astride;
    const float* Ar2 = Ar1 + 8 * astride;
#pragma unroll 1
    for (int t = 0; t < ntiles; ++t) {
        __syncthreads();                       // prior consumers of whp/wlp done
        sts_w16(whp, wlp, rw, tid);
        if (t + 1 < ntiles) ldg_w16(rw, W, (t + 1) * KT, krows, tid);
        __syncthreads();                       // tile ready
        int kA = t * KT + tg * 2;
        float2 a00 = *(const float2*)(Ar1 + kA);
        float2 a01 = *(const float2*)(Ar1 + kA + 8);
        float2 a10 = *(const float2*)(Ar2 + kA);
        float2 a11 = *(const float2*)(Ar2 + kA + 8);
        unsigned ahi[4], alo[4];
        split2(a00, ahi[0], alo[0]);
        split2(a10, ahi[1], alo[1]);
        split2(a01, ahi[2], alo[2]);
        split2(a11, ahi[3], alo[3]);
        const unsigned* wh0 = whp + tg * WSTRIDE;
        const unsigned* wh1 = whp + (tg + 4) * WSTRIDE;
        const unsigned* wl0 = wlp + tg * WSTRIDE;
        const unsigned* wl1 = wlp + (tg + 4) * WSTRIDE;
#pragma unroll
        for (int nt = 0; nt < 8; ++nt) {
            int coln = cbase + nt * 8 + gid;
            unsigned bh0 = wh0[coln], bh1 = wh1[coln];
            unsigned bl0 = wl0[coln], bl1 = wl1[coln];
            mma16(c[nt], ahi, bh0, bh1);
            mma16(c[nt], alo, bh0, bh1);
            mma16(c[nt], ahi, bl0, bl1);
        }
    }
}

__device__ __forceinline__ void zero_c(float c[8][4]) {
#pragma unroll
    for (int i = 0; i < 8; ++i)
#pragma unroll
        for (int j = 0; j < 4; ++j) c[i][j] = 0.f;
}

// ---------------------------------------------------------------------------
// Edge kernel (bf16x3 tensor-core path): 64 edges per block, 2 CTAs/SM.
// ---------------------------------------------------------------------------
__global__ __launch_bounds__(256, 2)
void edge_kernel(const float* __restrict__ feats, const float* __restrict__ x,
                 const float* __restrict__ edge_feats,
                 const int* __restrict__ src, const int* __restrict__ dst,
                 const float* __restrict__ eW1, const float* __restrict__ eb1,
                 const float* __restrict__ eg1, const float* __restrict__ ebn1,
                 const float* __restrict__ eW2, const float* __restrict__ eb2,
                 const float* __restrict__ cW1, const float* __restrict__ cb1,
                 const float* __restrict__ cW2, int E)
{
    extern __shared__ float sm[];
    float*    ein   = sm;                          // 64 x 324
    unsigned* whp   = (unsigned*)(ein + TILE * ESTRIDE);   // 8 x 136 u32
    unsigned* wlp   = whp + 8 * WSTRIDE;                   // 8 x 136 u32
    float*    xr    = (float*)(wlp + 8 * WSTRIDE);         // 64 x 3
    float2*   red   = (float2*)(xr + TILE * 3);    // [64][2] (sum,sumsq) per half
    float*    cvred = (float*)(red + TILE * 2);    // [64][2]
    int*      sdst  = (int*)(cvred + TILE * 2);    // 64
    int*      ssrc  = sdst + TILE;                 // 64
    float*    h1s   = ein;                         // overlay, 64 x 132
    float*    ms    = ein + TILE * HSTRIDE;        // overlay, 64 x 132

    const int tid = threadIdx.x;
    const int e0 = blockIdx.x * TILE;

    if (tid < TILE) {
        int e = e0 + tid;
        int s = 0, d = 0;
        if (e < E) { s = src[e]; d = dst[e]; }
        ssrc[tid] = s; sdst[tid] = d;
    }
    __syncthreads();

    // Gather features (L2-resident table)
    for (int idx = tid; idx < TILE * HID; idx += 256) {
        int r = idx >> 7, c = idx & 127;
        ein[r * ESTRIDE + c]       = feats[(size_t)ssrc[r] * HID + c];
        ein[r * ESTRIDE + 128 + c] = feats[(size_t)sdst[r] * HID + c];
    }
    for (int idx = tid; idx < TILE * 32; idx += 256) {
        int r = idx >> 5, c = idx & 31;
        int e = e0 + r;
        ein[r * ESTRIDE + 256 + c] = (e < E) ? edge_feats[(size_t)e * 32 + c] : 0.f;
    }
    // Geometry + RBF
    if (tid < TILE) {
        int e = e0 + tid;
        float rx = 0.f, ry = 0.f, rz = 0.f;
        if (e < E) {
            int s = ssrc[tid], d = sdst[tid];
            rx = x[3 * s + 0] - x[3 * d + 0];
            ry = x[3 * s + 1] - x[3 * d + 1];
            rz = x[3 * s + 2] - x[3 * d + 2];
            float nrm = sqrtf(rx * rx + ry * ry + rz * rz) + 1.0f;
            float inv = 1.0f / nrm;
            rx *= inv; ry *= inv; rz *= inv;
        }
        xr[tid * 3 + 0] = rx; xr[tid * 3 + 1] = ry; xr[tid * 3 + 2] = rz;
        float d2 = rx * rx + ry * ry + rz * rz;
        float sig = 1.0f;
#pragma unroll
        for (int i = 0; i < 15; ++i) {
            ein[tid * ESTRIDE + 288 + i] = expf(-d2 / sig);
            sig *= 1.5f;
        }
#pragma unroll
        for (int i = 303; i < 320; ++i) ein[tid * ESTRIDE + i] = 0.f;
    }
    // (gemm_mma's first __syncthreads orders the gather writes before MMA reads)

    const int lane = tid & 31, warp = tid >> 5;
    const int gid = lane >> 2, tg = lane & 3;
    const int rbase = (warp & 3) * 16;
    const int cbase = (warp >> 2) * 64;
    const int half = warp >> 2;
    const int r1 = rbase + gid, r2 = r1 + 8;

    float c[8][4];

    // ---- GEMM1: e_in(320, 303 real) @ eW1 -> 128   (19 k16 tiles)
    zero_c(c);
    gemm_mma(ein, ESTRIDE, eW1, 303, 19, whp, wlp, tid, rbase, cbase, gid, tg, c);

    // ---- bias + lrelu + LayerNorm -> h1s (overlay on ein)
    {
        float s1 = 0.f, q1 = 0.f, s2 = 0.f, q2 = 0.f;
#pragma unroll
        for (int nt = 0; nt < 8; ++nt) {
            int col = cbase + nt * 8 + 2 * tg;
            float2 b = *(const float2*)(eb1 + col);
            float t00 = lrelu(c[nt][0] + b.x), t01 = lrelu(c[nt][1] + b.y);
            float t10 = lrelu(c[nt][2] + b.x), t11 = lrelu(c[nt][3] + b.y);
            c[nt][0] = t00; c[nt][1] = t01; c[nt][2] = t10; c[nt][3] = t11;
            s1 += t00 + t01; q1 += t00 * t00 + t01 * t01;
            s2 += t10 + t11; q2 += t10 * t10 + t11 * t11;
        }
#pragma unroll
        for (int off = 1; off <= 2; off <<= 1) {
            s1 += __shfl_xor_sync(0xffffffffu, s1, off);
            q1 += __shfl_xor_sync(0xffffffffu, q1, off);
            s2 += __shfl_xor_sync(0xffffffffu, s2, off);
            q2 += __shfl_xor_sync(0xffffffffu, q2, off);
        }
        if (tg == 0) {
            red[r1 * 2 + half] = make_float2(s1, q1);
            red[r2 * 2 + half] = make_float2(s2, q2);
        }
        __syncthreads();   // red visible; all warps done reading ein -> overlay safe
        float2 u = red[r1 * 2 + 0], v = red[r1 * 2 + 1];
        float m1 = (u.x + v.x) * (1.f / 128.f);
        float inv1 = rsqrtf((u.y + v.y) * (1.f / 128.f) - m1 * m1 + 1e-5f);
        u = red[r2 * 2 + 0]; v = red[r2 * 2 + 1];
        float m2 = (u.x + v.x) * (1.f / 128.f);
        float inv2 = rsqrtf((u.y + v.y) * (1.f / 128.f) - m2 * m2 + 1e-5f);
#pragma unroll
        for (int nt = 0; nt < 8; ++nt) {
            int col = cbase + nt * 8 + 2 * tg;
            float2 g = *(const float2*)(eg1 + col);
            float2 bt = *(const float2*)(ebn1 + col);
            *(float2*)(h1s + r1 * HSTRIDE + col) =
                make_float2((c[nt][0] - m1) * inv1 * g.x + bt.x,
                            (c[nt][1] - m1) * inv1 * g.y + bt.y);
            *(float2*)(h1s + r2 * HSTRIDE + col) =
                make_float2((c[nt][2] - m2) * inv2 * g.x + bt.x,
                            (c[nt][3] - m2) * inv2 * g.y + bt.y);
        }
    }

    // ---- GEMM2: h1 @ eW2 -> m (lrelu) -> ms
    zero_c(c);
    gemm_mma(h1s, HSTRIDE, eW2, 128, 8, whp, wlp, tid, rbase, cbase, gid, tg, c);
    {
#pragma unroll
        for (int nt = 0; nt < 8; ++nt) {
            int col = cbase + nt * 8 + 2 * tg;
            float2 b = *(const float2*)(eb2 + col);
            *(float2*)(ms + r1 * HSTRIDE + col) =
                make_float2(lrelu(c[nt][0] + b.x), lrelu(c[nt][1] + b.y));
            *(float2*)(ms + r2 * HSTRIDE + col) =
                make_float2(lrelu(c[nt][2] + b.x), lrelu(c[nt][3] + b.y));
        }
    }

    // ---- GEMM3: t = lrelu(m @ cW1 + cb1); c_coef = t . cW2
    zero_c(c);
    gemm_mma(ms, HSTRIDE, cW1, 128, 8, whp, wlp, tid, rbase, cbase, gid, tg, c);
    {
        float p1 = 0.f, p2 = 0.f;
#pragma unroll
        for (int nt = 0; nt < 8; ++nt) {
            int col = cbase + nt * 8 + 2 * tg;
            float2 b = *(const float2*)(cb1 + col);
            float2 w = *(const float2*)(cW2 + col);
            p1 += lrelu(c[nt][0] + b.x) * w.x + lrelu(c[nt][1] + b.y) * w.y;
            p2 += lrelu(c[nt][2] + b.x) * w.x + lrelu(c[nt][3] + b.y) * w.y;
        }
#pragma unroll
        for (int off = 1; off <= 2; off <<= 1) {
            p1 += __shfl_xor_sync(0xffffffffu, p1, off);
            p2 += __shfl_xor_sync(0xffffffffu, p2, off);
        }
        if (tg == 0) {
            cvred[r1 * 2 + half] = p1;
            cvred[r2 * 2 + half] = p2;
        }
    }
    __syncthreads();

    // ---- Aggregation atomics (coalesced REDs over ms)
    for (int idx = tid; idx < TILE * 128; idx += 256) {
        int row = idx >> 7, col = idx & 127;
        int e = e0 + row;
        if (e < E)
            atomicAdd(g_aggr + (size_t)sdst[row] * 128 + col, ms[row * HSTRIDE + col]);
    }
    if (tid < TILE) {
        int e = e0 + tid;
        if (e < E) {
            float cv = cvred[tid * 2] + cvred[tid * 2 + 1];
            int dn = sdst[tid];
            atomicAdd(&g_xsum[(size_t)dn * 3 + 0], xr[tid * 3 + 0] * cv);
            atomicAdd(&g_xsum[(size_t)dn * 3 + 1], xr[tid * 3 + 1] * cv);
            atomicAdd(&g_xsum[(size_t)dn * 3 + 2], xr[tid * 3 + 2] * cv);
            atomicAdd(&g_cnt[dn], 1.0f);
        }
    }
}

// ===========================================================================
// Node kernel: unchanged SIMT f32x2 path (265us; not the bottleneck).
// ===========================================================================
typedef unsigned long long u64;

__device__ __forceinline__ u64 pack2(float v) {
    u64 p; asm("mov.b64 %0, {%1, %1};" : "=l"(p) : "f"(v)); return p;
}
__device__ __forceinline__ float2 unpack2(u64 v) {
    float2 f; asm("mov.b64 {%0, %1}, %2;" : "=f"(f.x), "=f"(f.y) : "l"(v)); return f;
}
__device__ __forceinline__ void ffma2(u64& d, u64 a, u64 b) {
    asm("fma.rn.f32x2 %0, %1, %2, %0;" : "+l"(d) : "l"(a), "l"(b));
}

__device__ __forceinline__ void gemm_tile_s(const float* __restrict__ A, int astride,
                                            const float* __restrict__ wt, int cb,
                                            u64 acc[4][4])
{
#pragma unroll
    for (int kq = 0; kq < 8; ++kq) {
        float4 a4[4];
#pragma unroll
        for (int r = 0; r < 4; ++r)
            a4[r] = *(const float4*)(A + r * astride + kq * 4);
#pragma unroll
        for (int k = 0; k < 4; ++k) {
            const float* wrow = wt + (kq * 4 + k) * 128 + cb;
            const ulonglong2 b0 = *(const ulonglong2*)(wrow);
            const ulonglong2 b1 = *(const ulonglong2*)(wrow + 4);
            u64 bp[4] = {b0.x, b0.y, b1.x, b1.y};
#pragma unroll
            for (int r = 0; r < 4; ++r) {
                float av = (k == 0) ? a4[r].x : (k == 1) ? a4[r].y
                         : (k == 2) ? a4[r].z : a4[r].w;
                u64 ap = pack2(av);
#pragma unroll
                for (int c = 0; c < 4; ++c)
                    ffma2(acc[r][c], ap, bp[c]);
            }
        }
    }
}

template<bool REMAP>
__device__ __forceinline__ void ldg_wt(float4 r[4], const float* __restrict__ W,
                                       int k0, int krows, int tid)
{
#pragma unroll
    for (int j = 0; j < 4; ++j) {
        int flat = (tid + j * 256) << 2;
        int kk = flat >> 7, c2 = flat & 127;
        int k = k0 + kk;
        if (REMAP) {
            int kr = (k < 256) ? k : k + 128;
            r[j] = *(const float4*)(W + (size_t)kr * 128 + c2);
        } else {
            r[j] = (k < krows) ? *(const float4*)(W + (size_t)k * 128 + c2)
                               : make_float4(0.f, 0.f, 0.f, 0.f);
        }
    }
}
__device__ __forceinline__ void sts_wt(float* __restrict__ wt, const float4 r[4], int tid)
{
#pragma unroll
    for (int j = 0; j < 4; ++j)
        *(float4*)(wt + ((tid + j * 256) << 2)) = r[j];
}
template<bool REMAP>
__device__ __forceinline__ void gemm_run(const float* __restrict__ A, int astride,
                                         const float* __restrict__ W, int krows, int ntiles,
                                         float* __restrict__ wt, int tid, int cb,
                                         u64 acc[4][4])
{
    float4 rw[4];
    ldg_wt<REMAP>(rw, W, 0, krows, tid);
#pragma unroll 1
    for (int t = 0; t < ntiles; ++t) {
        __syncthreads();
        sts_wt(wt, rw, tid);
        if (t + 1 < ntiles) ldg_wt<REMAP>(rw, W, (t + 1) * 32, krows, tid);
        __syncthreads();
        gemm_tile_s(A + t * 32, astride, wt, cb, acc);
    }
}
__device__ __forceinline__ void zero_acc(u64 acc[4][4]) {
#pragma unroll
    for (int r = 0; r < 4; ++r)
#pragma unroll
        for (int c = 0; c < 4; ++c) acc[r][c] = 0ull;
}
__device__ __forceinline__ void acc_to_v(const u64 acc[4], float v[8]) {
#pragma unroll
    for (int c = 0; c < 4; ++c) {
        float2 f = unpack2(acc[c]);
        v[2 * c] = f.x; v[2 * c + 1] = f.y;
    }
}

__global__ __launch_bounds__(256, 2)
void node_kernel(const float* __restrict__ feats, const float* __restrict__ orig,
                 const float* __restrict__ x,
                 const float* __restrict__ nng, const float* __restrict__ nnb,
                 const float* __restrict__ nW1, const float* __restrict__ nb1,
                 const float* __restrict__ ng1, const float* __restrict__ nbn1,
                 const float* __restrict__ nW2, const float* __restrict__ nb2,
                 float* __restrict__ out, int N)
{
    extern __shared__ float sm[];
    float* nin = sm;                      // 64 x 324 (320 used)
    float* wt  = nin + TILE * ESTRIDE;    // 32 x 128
    float* nh  = nin;                     // overlay, 64 x 132

    const int tid = threadIdx.x;
    const int n0 = blockIdx.x * TILE;

    for (int idx = tid; idx < TILE * 128; idx += 256) {
        int r = idx >> 7, c = idx & 127;
        int n = n0 + r;
        nin[r * ESTRIDE + c]       = (n < N) ? feats[(size_t)n * 128 + c] : 0.f;
        nin[r * ESTRIDE + 128 + c] = (n < N) ? g_aggr[(size_t)n * 128 + c] : 0.f;
    }
    for (int idx = tid; idx < TILE * 64; idx += 256) {
        int r = idx >> 6, c = idx & 63;
        int n = n0 + r;
        nin[r * ESTRIDE + 256 + c] = (n < N) ? orig[(size_t)n * 64 + c] : 0.f;
    }
    __syncthreads();

    const int lane = tid & 31, warp = tid >> 5;
    const int rg = lane >> 4;
    const int r0 = warp * 8 + rg * 4;
    const int cb = (lane & 15) * 8;

    {
        float4 g0 = *(const float4*)(nng + cb), g1v = *(const float4*)(nng + cb + 4);
        float gg[8] = {g0.x, g0.y, g0.z, g0.w, g1v.x, g1v.y, g1v.z, g1v.w};
        float4 q0 = *(const float4*)(nnb + cb), q1 = *(const float4*)(nnb + cb + 4);
        float qq[8] = {q0.x, q0.y, q0.z, q0.w, q1.x, q1.y, q1.z, q1.w};
#pragma unroll
        for (int rr = 0; rr < 4; ++rr) {
            float* rp = nin + (r0 + rr) * ESTRIDE + cb;
            float v[8]; float s = 0.f, q = 0.f;
#pragma unroll
            for (int c = 0; c < 8; ++c) { v[c] = rp[c]; s += v[c]; q += v[c] * v[c]; }
#pragma unroll
            for (int off = 8; off >= 1; off >>= 1) {
                s += __shfl_xor_sync(0xffffffffu, s, off);
                q += __shfl_xor_sync(0xffffffffu, q, off);
            }
            float mean = s * (1.f / 128.f);
            float var = q * (1.f / 128.f) - mean * mean;
            float inv = rsqrtf(var + 1e-5f);
#pragma unroll
            for (int c = 0; c < 8; ++c)
                rp[c] = (v[c] - mean) * inv * gg[c] + qq[c];
        }
    }
    __syncthreads();

    u64 acc[4][4];
    zero_acc(acc);
    gemm_run<true>(nin + r0 * ESTRIDE, ESTRIDE, nW1, 448, 10, wt, tid, cb, acc);
    __syncthreads();

    {
        float4 t0 = *(const float4*)(nb1 + cb), t1 = *(const float4*)(nb1 + cb + 4);
        float bb[8] = {t0.x, t0.y, t0.z, t0.w, t1.x, t1.y, t1.z, t1.w};
        float4 g0 = *(const float4*)(ng1 + cb), g1v = *(const float4*)(ng1 + cb + 4);
        float gg[8] = {g0.x, g0.y, g0.z, g0.w, g1v.x, g1v.y, g1v.z, g1v.w};
        float4 q0 = *(const float4*)(nbn1 + cb), q1 = *(const float4*)(nbn1 + cb + 4);
        float qq[8] = {q0.x, q0.y, q0.z, q0.w, q1.x, q1.y, q1.z, q1.w};
#pragma unroll
        for (int rr = 0; rr < 4; ++rr) {
            float v[8]; float s = 0.f, q = 0.f;
            acc_to_v(acc[rr], v);
#pragma unroll
            for (int c = 0; c < 8; ++c) {
                float t = lrelu(v[c] + bb[c]);
                v[c] = t; s += t; q += t * t;
            }
#pragma unroll
            for (int off = 8; off >= 1; off >>= 1) {
                s += __shfl_xor_sync(0xffffffffu, s, off);
                q += __shfl_xor_sync(0xffffffffu, q, off);
            }
            float mean = s * (1.f / 128.f);
            float var = q * (1.f / 128.f) - mean * mean;
            float inv = rsqrtf(var + 1e-5f);
            float* hp = nh + (r0 + rr) * HSTRIDE + cb;
#pragma unroll
            for (int c = 0; c < 8; ++c)
                hp[c] = (v[c] - mean) * inv * gg[c] + qq[c];
        }
    }

    zero_acc(acc);
    gemm_run<false>(nh + r0 * HSTRIDE, HSTRIDE, nW2, 128, 4, wt, tid, cb, acc);

    {
        float4 t0 = *(const float4*)(nb2 + cb), t1 = *(const float4*)(nb2 + cb + 4);
        float bb[8] = {t0.x, t0.y, t0.z, t0.w, t1.x, t1.y, t1.z, t1.w};
#pragma unroll
        for (int rr = 0; rr < 4; ++rr) {
            int n = n0 + r0 + rr;
            if (n < N) {
                float v[8];
                acc_to_v(acc[rr], v);
                const float* fp = feats + (size_t)n * 128 + cb;
                float* op = out + (size_t)n * 128 + cb;
#pragma unroll
                for (int c = 0; c < 8; ++c) {
                    float o = v[c] + bb[c];
                    op[c] = 0.75f * o + 0.25f * fp[c];
                }
            }
        }
    }
    if (tid < TILE) {
        int n = n0 + tid;
        if (n < N) {
            float cnt = g_cnt[n];
            if (cnt < 1.f) cnt = 1.f;
            float inv = 1.f / cnt;
            size_t base = (size_t)N * 128 + (size_t)n * 3;
            out[base + 0] = x[(size_t)n * 3 + 0] + g_xsum[(size_t)n * 3 + 0] * inv;
            out[base + 1] = x[(size_t)n * 3 + 1] + g_xsum[(size_t)n * 3 + 1] * inv;
            out[base + 2] = x[(size_t)n * 3 + 2] + g_xsum[(size_t)n * 3 + 2] * inv;
        }
    }
}

extern "C" void kernel_launch(void* const* d_in, const int* in_sizes, int n_in,
                              void* d_out, int out_size)
{
    const float* feats      = (const float*)d_in[0];
    const float* orig       = (const float*)d_in[1];
    const float* x          = (const float*)d_in[2];
    /* d_in[3] = x_orig, unused (X_CONN_INIT = 0) */
    const float* edge_feats = (const float*)d_in[4];
    const int*   src        = (const int*)d_in[5];
    const int*   dst        = (const int*)d_in[6];
    const float* eW1  = (const float*)d_in[7];
    const float* eb1  = (const float*)d_in[8];
    const float* eg1  = (const float*)d_in[9];
    const float* ebn1 = (const float*)d_in[10];
    const float* eW2  = (const float*)d_in[11];
    const float* eb2  = (const float*)d_in[12];
    const float* nng  = (const float*)d_in[13];
    const float* nnb  = (const float*)d_in[14];
    const float* nW1  = (const float*)d_in[15];
    const float* nb1  = (const float*)d_in[16];
    const float* ng1  = (const float*)d_in[17];
    const float* nbn1 = (const float*)d_in[18];
    const float* nW2  = (const float*)d_in[19];
    const float* nb2  = (const float*)d_in[20];
    const float* cW1  = (const float*)d_in[21];
    const float* cb1  = (const float*)d_in[22];
    const float* cW2  = (const float*)d_in[23];

    const int N = in_sizes[0] / HID;
    const int E = in_sizes[5];

    void *aggr_p, *xs_p, *cnt_p;
    cudaGetSymbolAddress(&aggr_p, g_aggr);
    cudaGetSymbolAddress(&xs_p, g_xsum);
    cudaGetSymbolAddress(&cnt_p, g_cnt);
    cudaMemsetAsync(aggr_p, 0, (size_t)N * OUT * sizeof(float), 0);
    cudaMemsetAsync(xs_p, 0, (size_t)N * 3 * sizeof(float), 0);
    cudaMemsetAsync(cnt_p, 0, (size_t)N * sizeof(float), 0);

    // edge smem: ein + 2 packed weight tiles + xr + red + cvred + idx
    const int SMEM_E = (TILE * ESTRIDE + 2 * 8 * WSTRIDE + TILE * 3
                        + TILE * 2 * 2 + TILE * 2) * 4
                       + TILE * 2 * (int)sizeof(int);
    const int SMEM_N = (TILE * ESTRIDE + 32 * 128) * 4;
    cudaFuncSetAttribute(edge_kernel, cudaFuncAttributeMaxDynamicSharedMemorySize, SMEM_E);
    cudaFuncSetAttribute(node_kernel, cudaFuncAttributeMaxDynamicSharedMemorySize, SMEM_N);

    int eblocks = (E + TILE - 1) / TILE;
    edge_kernel<<<eblocks, 256, SMEM_E>>>(feats, x, edge_feats, src, dst,
                                          eW1, eb1, eg1, ebn1, eW2, eb2,
                                          cW1, cb1, cW2, E);

    int nblocks = (N + TILE - 1) / TILE;
    node_kernel<<<nblocks, 256, SMEM_N>>>(feats, orig, x, nng, nnb,
                                          nW1, nb1, ng1, nbn1, nW2, nb2,
                                          (float*)d_out, N);
}

// round 8
// speedup vs baseline: 3.7764x; 1.0969x over previous
#include <cuda_runtime.h>
#include <cuda_bf16.h>
#include <math.h>

#define HID 128
#define OUT 128
#define NMAX 50000
#define ESTRIDE 324   // edge/node input stride
#define HSTRIDE 132   // hidden buffer stride
#define WSTRIDE 136   // packed-weight tile stride in u32 (conflict-free B frags)
#define KT 16         // k-tile rows (one m16n8k16 chunk)
#define TILE 64
#define WBUF (16 * WSTRIDE)   // u32 per weight buffer (hi 8x136 + lo 8x136)

// Scratch (static __device__ globals; no allocations anywhere)
__device__ float g_aggr[(size_t)NMAX * OUT];
__device__ float g_xsum[(size_t)NMAX * 3];
__device__ float g_cnt[NMAX];

// Prepacked bf16 hi/lo weights (u32 = bf16x2 over k-pairs)
__device__ unsigned g_eW1h[152 * 128], g_eW1l[152 * 128];   // 19 tiles
__device__ unsigned g_eW2h[64 * 128],  g_eW2l[64 * 128];    // 8 tiles
__device__ unsigned g_cW1h[64 * 128],  g_cW1l[64 * 128];    // 8 tiles
__device__ unsigned g_nW1h[160 * 128], g_nW1l[160 * 128];   // 20 tiles (mha block removed)
__device__ unsigned g_nW2h[64 * 128],  g_nW2l[64 * 128];    // 8 tiles

__device__ __forceinline__ float lrelu(float v) { return v > 0.f ? v : 0.01f * v; }

// ---------------- bf16 split helpers ----------------
__device__ __forceinline__ unsigned bf16x2_pack(float a, float b) {
    unsigned r;
    asm("cvt.rn.bf16x2.f32 %0, %1, %2;" : "=r"(r) : "f"(b), "f"(a));
    return r;
}
__device__ __forceinline__ float bf16_lo_f(unsigned p) { return __uint_as_float(p << 16); }
__device__ __forceinline__ float bf16_hi_f(unsigned p) { return __uint_as_float(p & 0xffff0000u); }

__device__ __forceinline__ void split2(float2 a, unsigned& hi, unsigned& lo) {
    hi = bf16x2_pack(a.x, a.y);
    float r0 = a.x - bf16_lo_f(hi);
    float r1 = a.y - bf16_hi_f(hi);
    lo = bf16x2_pack(r0, r1);
}

// m16n8k16 bf16 MMA, C += A*B
__device__ __forceinline__ void mma16(float c[4], const unsigned a[4], unsigned b0, unsigned b1) {
    asm("mma.sync.aligned.m16n8k16.row.col.f32.bf16.bf16.f32 "
        "{%0,%1,%2,%3}, {%4,%5,%6,%7}, {%8,%9}, {%0,%1,%2,%3};"
        : "+f"(c[0]), "+f"(c[1]), "+f"(c[2]), "+f"(c[3])
        : "r"(a[0]), "r"(a[1]), "r"(a[2]), "r"(a[3]), "r"(b0), "r"(b1));
}

// ---------------- prepack kernel: fp32 weights -> packed bf16 hi/lo ----------
__global__ void prepack_kernel(const float* __restrict__ eW1, const float* __restrict__ eW2,
                               const float* __restrict__ cW1, const float* __restrict__ nW1,
                               const float* __restrict__ nW2)
{
    int idx = blockIdx.x * 256 + threadIdx.x;
    if (idx >= 504 * 128) return;
    int col = idx & 127, p = idx >> 7;
    float a, b;
    unsigned *H, *L;
    int o;
    if (p < 152) {                       // eW1: 303 real rows, pad to 304
        int k = 2 * p;
        a = eW1[(size_t)k * 128 + col];
        b = (k + 1 < 303) ? eW1[(size_t)(k + 1) * 128 + col] : 0.f;
        H = g_eW1h; L = g_eW1l; o = p * 128 + col;
    } else if (p < 216) {                // eW2: 128 rows
        int k = 2 * (p - 152);
        a = eW2[(size_t)k * 128 + col];
        b = eW2[(size_t)(k + 1) * 128 + col];
        H = g_eW2h; L = g_eW2l; o = (p - 152) * 128 + col;
    } else if (p < 280) {                // cW1: 128 rows
        int k = 2 * (p - 216);
        a = cW1[(size_t)k * 128 + col];
        b = cW1[(size_t)(k + 1) * 128 + col];
        H = g_cW1h; L = g_cW1l; o = (p - 216) * 128 + col;
    } else if (p < 440) {                // nW1: 320 logical rows (skip zero mha block)
        int k = 2 * (p - 280);
        int r0 = (k < 256) ? k : k + 128;
        int r1 = (k + 1 < 256) ? (k + 1) : (k + 1 + 128);
        a = nW1[(size_t)r0 * 128 + col];
        b = nW1[(size_t)r1 * 128 + col];
        H = g_nW1h; L = g_nW1l; o = (p - 280) * 128 + col;
    } else {                             // nW2: 128 rows
        int k = 2 * (p - 440);
        a = nW2[(size_t)k * 128 + col];
        b = nW2[(size_t)(k + 1) * 128 + col];
        H = g_nW2h; L = g_nW2l; o = (p - 440) * 128 + col;
    }
    unsigned h = bf16x2_pack(a, b);
    float ra = a - bf16_lo_f(h), rb = b - bf16_hi_f(h);
    H[o] = h;
    L[o] = bf16x2_pack(ra, rb);
}

// ---------------- packed-weight tile load/store ----------------
__device__ __forceinline__ void ldg_pk(uint4& rh, uint4& rl,
                                       const unsigned* __restrict__ Wh,
                                       const unsigned* __restrict__ Wl, int t, int tid)
{
    int p = tid >> 5, c = (tid & 31) * 4;
    size_t off = (size_t)(t * 8 + p) * 128 + c;
    rh = *(const uint4*)(Wh + off);
    rl = *(const uint4*)(Wl + off);
}
__device__ __forceinline__ void sts_pk(unsigned* __restrict__ buf,
                                       const uint4& rh, const uint4& rl, int tid)
{
    int p = tid >> 5, c = (tid & 31) * 4;
    *(uint4*)(buf + p * WSTRIDE + c) = rh;
    *(uint4*)(buf + 8 * WSTRIDE + p * WSTRIDE + c) = rl;
}

// ---------------- warp-level split-bf16 GEMM (double-buffered weights) -------
// Accumulates A[rbase..rbase+15, :] @ W[:, cbase..cbase+63] into c[8][4].
__device__ __forceinline__ void gemm_mma(const float* __restrict__ As, int astride,
                                         const unsigned* __restrict__ Wh,
                                         const unsigned* __restrict__ Wl, int ntiles,
                                         unsigned* __restrict__ wb,
                                         int tid, int rbase, int cbase, int gid, int tg,
                                         float c[8][4])
{
    uint4 rh, rl;
    ldg_pk(rh, rl, Wh, Wl, 0, tid);
    const float* Ar1 = As + (size_t)(rbase + gid) * astride;
    const float* Ar2 = Ar1 + 8 * astride;
    __syncthreads();                      // prior consumers of wb / producers of As done
    sts_pk(wb, rh, rl, tid);
    if (ntiles > 1) ldg_pk(rh, rl, Wh, Wl, 1, tid);
#pragma unroll 1
    for (int t = 0; t < ntiles; ++t) {
        __syncthreads();                  // tile t visible; all warps done with tile t-1
        const unsigned* whp = wb + (t & 1) * WBUF;
        const unsigned* wlp = whp + 8 * WSTRIDE;
        int kA = t * KT + tg * 2;
        float2 a00 = *(const float2*)(Ar1 + kA);
        float2 a01 = *(const float2*)(Ar1 + kA + 8);
        float2 a10 = *(const float2*)(Ar2 + kA);
        float2 a11 = *(const float2*)(Ar2 + kA + 8);
        unsigned ahi[4], alo[4];
        split2(a00, ahi[0], alo[0]);
        split2(a10, ahi[1], alo[1]);
        split2(a01, ahi[2], alo[2]);
        split2(a11, ahi[3], alo[3]);
        const unsigned* wh0 = whp + tg * WSTRIDE;
        const unsigned* wh1 = whp + (tg + 4) * WSTRIDE;
        const unsigned* wl0 = wlp + tg * WSTRIDE;
        const unsigned* wl1 = wlp + (tg + 4) * WSTRIDE;
#pragma unroll
        for (int nt = 0; nt < 8; ++nt) {
            int coln = cbase + nt * 8 + gid;
            unsigned bh0 = wh0[coln], bh1 = wh1[coln];
            unsigned bl0 = wl0[coln], bl1 = wl1[coln];
            mma16(c[nt], ahi, bh0, bh1);
            mma16(c[nt], alo, bh0, bh1);
            mma16(c[nt], ahi, bl0, bl1);
        }
        if (t + 1 < ntiles) {
            sts_pk(wb + ((t + 1) & 1) * WBUF, rh, rl, tid);
            if (t + 2 < ntiles) ldg_pk(rh, rl, Wh, Wl, t + 2, tid);
        }
    }
}

__device__ __forceinline__ void zero_c(float c[8][4]) {
#pragma unroll
    for (int i = 0; i < 8; ++i)
#pragma unroll
        for (int j = 0; j < 4; ++j) c[i][j] = 0.f;
}

// ---------------------------------------------------------------------------
// Edge kernel: 64 edges per block, 2 CTAs/SM.
// ---------------------------------------------------------------------------
__global__ __launch_bounds__(256, 2)
void edge_kernel(const float* __restrict__ feats, const float* __restrict__ x,
                 const float* __restrict__ edge_feats,
                 const int* __restrict__ src, const int* __restrict__ dst,
                 const float* __restrict__ eb1, const float* __restrict__ eg1,
                 const float* __restrict__ ebn1, const float* __restrict__ eb2,
                 const float* __restrict__ cb1, const float* __restrict__ cW2, int E)
{
    extern __shared__ float sm[];
    float*    ein   = sm;                                   // 64 x 324
    unsigned* wb    = (unsigned*)(ein + TILE * ESTRIDE);    // 2 x WBUF u32
    float*    xr    = (float*)(wb + 2 * WBUF);              // 64 x 3
    float2*   red   = (float2*)(xr + TILE * 3);             // [64][2]
    float*    cvred = (float*)(red + TILE * 2);             // [64][2]
    int*      sdst  = (int*)(cvred + TILE * 2);             // 64
    int*      ssrc  = sdst + TILE;                          // 64
    float*    h1s   = ein;                                  // overlay, 64 x 132
    float*    ms    = ein + TILE * HSTRIDE;                 // overlay, 64 x 132

    const int tid = threadIdx.x;
    const int e0 = blockIdx.x * TILE;

    if (tid < TILE) {
        int e = e0 + tid;
        int s = 0, d = 0;
        if (e < E) { s = src[e]; d = dst[e]; }
        ssrc[tid] = s; sdst[tid] = d;
    }
    __syncthreads();

    // Gather features (L2-resident table)
    for (int idx = tid; idx < TILE * HID; idx += 256) {
        int r = idx >> 7, c = idx & 127;
        ein[r * ESTRIDE + c]       = feats[(size_t)ssrc[r] * HID + c];
        ein[r * ESTRIDE + 128 + c] = feats[(size_t)sdst[r] * HID + c];
    }
    for (int idx = tid; idx < TILE * 32; idx += 256) {
        int r = idx >> 5, c = idx & 31;
        int e = e0 + r;
        ein[r * ESTRIDE + 256 + c] = (e < E) ? edge_feats[(size_t)e * 32 + c] : 0.f;
    }
    // Geometry + RBF
    if (tid < TILE) {
        int e = e0 + tid;
        float rx = 0.f, ry = 0.f, rz = 0.f;
        if (e < E) {
            int s = ssrc[tid], d = sdst[tid];
            rx = x[3 * s + 0] - x[3 * d + 0];
            ry = x[3 * s + 1] - x[3 * d + 1];
            rz = x[3 * s + 2] - x[3 * d + 2];
            float nrm = sqrtf(rx * rx + ry * ry + rz * rz) + 1.0f;
            float inv = 1.0f / nrm;
            rx *= inv; ry *= inv; rz *= inv;
        }
        xr[tid * 3 + 0] = rx; xr[tid * 3 + 1] = ry; xr[tid * 3 + 2] = rz;
        float d2 = rx * rx + ry * ry + rz * rz;
        float sig = 1.0f;
#pragma unroll
        for (int i = 0; i < 15; ++i) {
            ein[tid * ESTRIDE + 288 + i] = expf(-d2 / sig);
            sig *= 1.5f;
        }
#pragma unroll
        for (int i = 303; i < 320; ++i) ein[tid * ESTRIDE + i] = 0.f;
    }
    // (gemm_mma's internal syncs order the gather writes before MMA reads)

    const int lane = tid & 31, warp = tid >> 5;
    const int gid = lane >> 2, tg = lane & 3;
    const int rbase = (warp & 3) * 16;
    const int cbase = (warp >> 2) * 64;
    const int half = warp >> 2;
    const int r1 = rbase + gid, r2 = r1 + 8;

    float c[8][4];

    // ---- GEMM1: e_in(304 padded, 303 real) @ eW1 -> 128   (19 k16 tiles)
    zero_c(c);
    gemm_mma(ein, ESTRIDE, g_eW1h, g_eW1l, 19, wb, tid, rbase, cbase, gid, tg, c);

    // ---- bias + lrelu + LayerNorm -> h1s (overlay on ein)
    {
        float s1 = 0.f, q1 = 0.f, s2 = 0.f, q2 = 0.f;
#pragma unroll
        for (int nt = 0; nt < 8; ++nt) {
            int col = cbase + nt * 8 + 2 * tg;
            float2 b = *(const float2*)(eb1 + col);
            float t00 = lrelu(c[nt][0] + b.x), t01 = lrelu(c[nt][1] + b.y);
            float t10 = lrelu(c[nt][2] + b.x), t11 = lrelu(c[nt][3] + b.y);
            c[nt][0] = t00; c[nt][1] = t01; c[nt][2] = t10; c[nt][3] = t11;
            s1 += t00 + t01; q1 += t00 * t00 + t01 * t01;
            s2 += t10 + t11; q2 += t10 * t10 + t11 * t11;
        }
#pragma unroll
        for (int off = 1; off <= 2; off <<= 1) {
            s1 += __shfl_xor_sync(0xffffffffu, s1, off);
            q1 += __shfl_xor_sync(0xffffffffu, q1, off);
            s2 += __shfl_xor_sync(0xffffffffu, s2, off);
            q2 += __shfl_xor_sync(0xffffffffu, q2, off);
        }
        if (tg == 0) {
            red[r1 * 2 + half] = make_float2(s1, q1);
            red[r2 * 2 + half] = make_float2(s2, q2);
        }
        __syncthreads();   // red visible; all warps done reading ein -> overlay safe
        float2 u = red[r1 * 2 + 0], v = red[r1 * 2 + 1];
        float m1 = (u.x + v.x) * (1.f / 128.f);
        float inv1 = rsqrtf((u.y + v.y) * (1.f / 128.f) - m1 * m1 + 1e-5f);
        u = red[r2 * 2 + 0]; v = red[r2 * 2 + 1];
        float m2 = (u.x + v.x) * (1.f / 128.f);
        float inv2 = rsqrtf((u.y + v.y) * (1.f / 128.f) - m2 * m2 + 1e-5f);
#pragma unroll
        for (int nt = 0; nt < 8; ++nt) {
            int col = cbase + nt * 8 + 2 * tg;
            float2 g = *(const float2*)(eg1 + col);
            float2 bt = *(const float2*)(ebn1 + col);
            *(float2*)(h1s + r1 * HSTRIDE + col) =
                make_float2((c[nt][0] - m1) * inv1 * g.x + bt.x,
                            (c[nt][1] - m1) * inv1 * g.y + bt.y);
            *(float2*)(h1s + r2 * HSTRIDE + col) =
                make_float2((c[nt][2] - m2) * inv2 * g.x + bt.x,
                            (c[nt][3] - m2) * inv2 * g.y + bt.y);
        }
    }

    // ---- GEMM2: h1 @ eW2 -> m (lrelu) -> ms
    zero_c(c);
    gemm_mma(h1s, HSTRIDE, g_eW2h, g_eW2l, 8, wb, tid, rbase, cbase, gid, tg, c);
    {
#pragma unroll
        for (int nt = 0; nt < 8; ++nt) {
            int col = cbase + nt * 8 + 2 * tg;
            float2 b = *(const float2*)(eb2 + col);
            *(float2*)(ms + r1 * HSTRIDE + col) =
                make_float2(lrelu(c[nt][0] + b.x), lrelu(c[nt][1] + b.y));
            *(float2*)(ms + r2 * HSTRIDE + col) =
                make_float2(lrelu(c[nt][2] + b.x), lrelu(c[nt][3] + b.y));
        }
    }

    // ---- GEMM3: t = lrelu(m @ cW1 + cb1); c_coef = t . cW2
    zero_c(c);
    gemm_mma(ms, HSTRIDE, g_cW1h, g_cW1l, 8, wb, tid, rbase, cbase, gid, tg, c);
    {
        float p1 = 0.f, p2 = 0.f;
#pragma unroll
        for (int nt = 0; nt < 8; ++nt) {
            int col = cbase + nt * 8 + 2 * tg;
            float2 b = *(const float2*)(cb1 + col);
            float2 w = *(const float2*)(cW2 + col);
            p1 += lrelu(c[nt][0] + b.x) * w.x + lrelu(c[nt][1] + b.y) * w.y;
            p2 += lrelu(c[nt][2] + b.x) * w.x + lrelu(c[nt][3] + b.y) * w.y;
        }
#pragma unroll
        for (int off = 1; off <= 2; off <<= 1) {
            p1 += __shfl_xor_sync(0xffffffffu, p1, off);
            p2 += __shfl_xor_sync(0xffffffffu, p2, off);
        }
        if (tg == 0) {
            cvred[r1 * 2 + half] = p1;
            cvred[r2 * 2 + half] = p2;
        }
    }
    __syncthreads();

    // ---- Aggregation atomics (coalesced REDs over ms)
    for (int idx = tid; idx < TILE * 128; idx += 256) {
        int row = idx >> 7, col = idx & 127;
        int e = e0 + row;
        if (e < E)
            atomicAdd(g_aggr + (size_t)sdst[row] * 128 + col, ms[row * HSTRIDE + col]);
    }
    if (tid < TILE) {
        int e = e0 + tid;
        if (e < E) {
            float cv = cvred[tid * 2] + cvred[tid * 2 + 1];
            int dn = sdst[tid];
            atomicAdd(&g_xsum[(size_t)dn * 3 + 0], xr[tid * 3 + 0] * cv);
            atomicAdd(&g_xsum[(size_t)dn * 3 + 1], xr[tid * 3 + 1] * cv);
            atomicAdd(&g_xsum[(size_t)dn * 3 + 2], xr[tid * 3 + 2] * cv);
            atomicAdd(&g_cnt[dn], 1.0f);
        }
    }
}

// ---------------------------------------------------------------------------
// Node kernel (bf16x3 tensor-core path): 64 nodes per block, 2 CTAs/SM.
// ---------------------------------------------------------------------------
__global__ __launch_bounds__(256, 2)
void node_kernel(const float* __restrict__ feats, const float* __restrict__ orig,
                 const float* __restrict__ x,
                 const float* __restrict__ nng, const float* __restrict__ nnb,
                 const float* __restrict__ nb1, const float* __restrict__ ng1,
                 const float* __restrict__ nbn1, const float* __restrict__ nb2,
                 float* __restrict__ out, int N)
{
    extern __shared__ float sm[];
    float*    nin = sm;                                   // 64 x 324 (320 used)
    unsigned* wb  = (unsigned*)(nin + TILE * ESTRIDE);    // 2 x WBUF u32
    float2*   red = (float2*)(wb + 2 * WBUF);             // [64][2]
    float*    nh  = nin;                                  // overlay, 64 x 132

    const int tid = threadIdx.x;
    const int n0 = blockIdx.x * TILE;

    for (int idx = tid; idx < TILE * 128; idx += 256) {
        int r = idx >> 7, c = idx & 127;
        int n = n0 + r;
        nin[r * ESTRIDE + c]       = (n < N) ? feats[(size_t)n * 128 + c] : 0.f;
        nin[r * ESTRIDE + 128 + c] = (n < N) ? g_aggr[(size_t)n * 128 + c] : 0.f;
    }
    for (int idx = tid; idx < TILE * 64; idx += 256) {
        int r = idx >> 6, c = idx & 63;
        int n = n0 + r;
        nin[r * ESTRIDE + 256 + c] = (n < N) ? orig[(size_t)n * 64 + c] : 0.f;
    }
    __syncthreads();

    const int lane = tid & 31, warp = tid >> 5;

    // LayerNorm(feats) in place on cols 0..127 (SIMT; rows spread over warps)
    {
        const int rg = lane >> 4;
        const int r0s = warp * 8 + rg * 4;
        const int cb = (lane & 15) * 8;
        float4 g0 = *(const float4*)(nng + cb), g1v = *(const float4*)(nng + cb + 4);
        float gg[8] = {g0.x, g0.y, g0.z, g0.w, g1v.x, g1v.y, g1v.z, g1v.w};
        float4 q0 = *(const float4*)(nnb + cb), q1 = *(const float4*)(nnb + cb + 4);
        float qq[8] = {q0.x, q0.y, q0.z, q0.w, q1.x, q1.y, q1.z, q1.w};
#pragma unroll
        for (int rr = 0; rr < 4; ++rr) {
            float* rp = nin + (r0s + rr) * ESTRIDE + cb;
            float v[8]; float s = 0.f, q = 0.f;
#pragma unroll
            for (int cc = 0; cc < 8; ++cc) { v[cc] = rp[cc]; s += v[cc]; q += v[cc] * v[cc]; }
#pragma unroll
            for (int off = 8; off >= 1; off >>= 1) {
                s += __shfl_xor_sync(0xffffffffu, s, off);
                q += __shfl_xor_sync(0xffffffffu, q, off);
            }
            float mean = s * (1.f / 128.f);
            float var = q * (1.f / 128.f) - mean * mean;
            float inv = rsqrtf(var + 1e-5f);
#pragma unroll
            for (int cc = 0; cc < 8; ++cc)
                rp[cc] = (v[cc] - mean) * inv * gg[cc] + qq[cc];
        }
    }

    const int gid = lane >> 2, tg = lane & 3;
    const int rbase = (warp & 3) * 16;
    const int cbase = (warp >> 2) * 64;
    const int half = warp >> 2;
    const int r1 = rbase + gid, r2 = r1 + 8;

    float c[8][4];

    // GEMM1: nin(320) @ nW1(remapped) -> 128   (20 k16 tiles)
    zero_c(c);
    gemm_mma(nin, ESTRIDE, g_nW1h, g_nW1l, 20, wb, tid, rbase, cbase, gid, tg, c);

    // bias + lrelu + LN -> nh (overlay)
    {
        float s1 = 0.f, q1 = 0.f, s2 = 0.f, q2 = 0.f;
#pragma unroll
        for (int nt = 0; nt < 8; ++nt) {
            int col = cbase + nt * 8 + 2 * tg;
            float2 b = *(const float2*)(nb1 + col);
            float t00 = lrelu(c[nt][0] + b.x), t01 = lrelu(c[nt][1] + b.y);
            float t10 = lrelu(c[nt][2] + b.x), t11 = lrelu(c[nt][3] + b.y);
            c[nt][0] = t00; c[nt][1] = t01; c[nt][2] = t10; c[nt][3] = t11;
            s1 += t00 + t01; q1 += t00 * t00 + t01 * t01;
            s2 += t10 + t11; q2 += t10 * t10 + t11 * t11;
        }
#pragma unroll
        for (int off = 1; off <= 2; off <<= 1) {
            s1 += __shfl_xor_sync(0xffffffffu, s1, off);
            q1 += __shfl_xor_sync(0xffffffffu, q1, off);
            s2 += __shfl_xor_sync(0xffffffffu, s2, off);
            q2 += __shfl_xor_sync(0xffffffffu, q2, off);
        }
        if (tg == 0) {
            red[r1 * 2 + half] = make_float2(s1, q1);
            red[r2 * 2 + half] = make_float2(s2, q2);
        }
        __syncthreads();   // red visible; all warps done reading nin -> overlay safe
        float2 u = red[r1 * 2 + 0], v = red[r1 * 2 + 1];
        float m1 = (u.x + v.x) * (1.f / 128.f);
        float inv1 = rsqrtf((u.y + v.y) * (1.f / 128.f) - m1 * m1 + 1e-5f);
        u = red[r2 * 2 + 0]; v = red[r2 * 2 + 1];
        float m2 = (u.x + v.x) * (1.f / 128.f);
        float inv2 = rsqrtf((u.y + v.y) * (1.f / 128.f) - m2 * m2 + 1e-5f);
#pragma unroll
        for (int nt = 0; nt < 8; ++nt) {
            int col = cbase + nt * 8 + 2 * tg;
            float2 g = *(const float2*)(ng1 + col);
            float2 bt = *(const float2*)(nbn1 + col);
            *(float2*)(nh + r1 * HSTRIDE + col) =
                make_float2((c[nt][0] - m1) * inv1 * g.x + bt.x,
                            (c[nt][1] - m1) * inv1 * g.y + bt.y);
            *(float2*)(nh + r2 * HSTRIDE + col) =
                make_float2((c[nt][2] - m2) * inv2 * g.x + bt.x,
                            (c[nt][3] - m2) * inv2 * g.y + bt.y);
        }
    }

    // GEMM2: nh @ nW2 -> out
    zero_c(c);
    gemm_mma(nh, HSTRIDE, g_nW2h, g_nW2l, 8, wb, tid, rbase, cbase, gid, tg, c);

    {
        int n1 = n0 + r1, n2 = n0 + r2;
#pragma unroll
        for (int nt = 0; nt < 8; ++nt) {
            int col = cbase + nt * 8 + 2 * tg;
            float2 b = *(const float2*)(nb2 + col);
            if (n1 < N) {
                float2 f = *(const float2*)(feats + (size_t)n1 * 128 + col);
                *(float2*)(out + (size_t)n1 * 128 + col) =
                    make_float2(0.75f * (c[nt][0] + b.x) + 0.25f * f.x,
                                0.75f * (c[nt][1] + b.y) + 0.25f * f.y);
            }
            if (n2 < N) {
                float2 f = *(const float2*)(feats + (size_t)n2 * 128 + col);
                *(float2*)(out + (size_t)n2 * 128 + col) =
                    make_float2(0.75f * (c[nt][2] + b.x) + 0.25f * f.x,
                                0.75f * (c[nt][3] + b.y) + 0.25f * f.y);
            }
        }
    }
    if (tid < TILE) {
        int n = n0 + tid;
        if (n < N) {
            float cnt = g_cnt[n];
            if (cnt < 1.f) cnt = 1.f;
            float inv = 1.f / cnt;
            size_t base = (size_t)N * 128 + (size_t)n * 3;
            out[base + 0] = x[(size_t)n * 3 + 0] + g_xsum[(size_t)n * 3 + 0] * inv;
            out[base + 1] = x[(size_t)n * 3 + 1] + g_xsum[(size_t)n * 3 + 1] * inv;
            out[base + 2] = x[(size_t)n * 3 + 2] + g_xsum[(size_t)n * 3 + 2] * inv;
        }
    }
}

extern "C" void kernel_launch(void* const* d_in, const int* in_sizes, int n_in,
                              void* d_out, int out_size)
{
    const float* feats      = (const float*)d_in[0];
    const float* orig       = (const float*)d_in[1];
    const float* x          = (const float*)d_in[2];
    /* d_in[3] = x_orig, unused (X_CONN_INIT = 0) */
    const float* edge_feats = (const float*)d_in[4];
    const int*   src        = (const int*)d_in[5];
    const int*   dst        = (const int*)d_in[6];
    const float* eW1  = (const float*)d_in[7];
    const float* eb1  = (const float*)d_in[8];
    const float* eg1  = (const float*)d_in[9];
    const float* ebn1 = (const float*)d_in[10];
    const float* eW2  = (const float*)d_in[11];
    const float* eb2  = (const float*)d_in[12];
    const float* nng  = (const float*)d_in[13];
    const float* nnb  = (const float*)d_in[14];
    const float* nW1  = (const float*)d_in[15];
    const float* nb1  = (const float*)d_in[16];
    const float* ng1  = (const float*)d_in[17];
    const float* nbn1 = (const float*)d_in[18];
    const float* nW2  = (const float*)d_in[19];
    const float* nb2  = (const float*)d_in[20];
    const float* cW1  = (const float*)d_in[21];
    const float* cb1  = (const float*)d_in[22];
    const float* cW2  = (const float*)d_in[23];

    const int N = in_sizes[0] / HID;
    const int E = in_sizes[5];

    void *aggr_p, *xs_p, *cnt_p;
    cudaGetSymbolAddress(&aggr_p, g_aggr);
    cudaGetSymbolAddress(&xs_p, g_xsum);
    cudaGetSymbolAddress(&cnt_p, g_cnt);
    cudaMemsetAsync(aggr_p, 0, (size_t)N * OUT * sizeof(float), 0);
    cudaMemsetAsync(xs_p, 0, (size_t)N * 3 * sizeof(float), 0);
    cudaMemsetAsync(cnt_p, 0, (size_t)N * sizeof(float), 0);

    prepack_kernel<<<252, 256>>>(eW1, eW2, cW1, nW1, nW2);

    const int SMEM_E = (TILE * ESTRIDE + 2 * WBUF + TILE * 3
                        + TILE * 2 * 2 + TILE * 2) * 4
                       + TILE * 2 * (int)sizeof(int);
    const int SMEM_N = (TILE * ESTRIDE + 2 * WBUF + TILE * 2 * 2) * 4;
    cudaFuncSetAttribute(edge_kernel, cudaFuncAttributeMaxDynamicSharedMemorySize, SMEM_E);
    cudaFuncSetAttribute(node_kernel, cudaFuncAttributeMaxDynamicSharedMemorySize, SMEM_N);

    int eblocks = (E + TILE - 1) / TILE;
    edge_kernel<<<eblocks, 256, SMEM_E>>>(feats, x, edge_feats, src, dst,
                                          eb1, eg1, ebn1, eb2, cb1, cW2, E);

    int nblocks = (N + TILE - 1) / TILE;
    node_kernel<<<nblocks, 256, SMEM_N>>>(feats, orig, x, nng, nnb,
                                          nb1, ng1, nbn1, nb2,
                                          (float*)d_out, N);
}